// round 13
// baseline (speedup 1.0000x reference)
#include <cuda_runtime.h>
#include <cuda_bf16.h>
#include <cstdint>

#define B_  16
#define S_  128
#define T_  64
#define H_  128
#define FF_ 256
#define M0_ (B_*S_*T_)
#define MS_ (B_*S_)
#define SCALE_ 0.25f

#if defined(__CUDA_ARCH__) && (defined(__CUDA_ARCH_FEAT_SM103_ALL) || \
    defined(__CUDA_ARCH_FEAT_SM100_ALL) || defined(__CUDA_ARCH_SPECIFIC__) || \
    defined(__CUDA_ARCH_FAMILY_SPECIFIC__))
#define TC_OK 1
#else
#define TC_OK 0
#endif

__device__ float g_x  [(size_t)M0_ * H_];
__device__ float g_tmp[(size_t)M0_ * H_];
__device__ float g_q  [(size_t)M0_ * H_];
__device__ float g_h  [(size_t)M0_ * FF_];
__device__ float g_xs [(size_t)MS_ * H_];
__device__ float g_qs [(size_t)MS_ * H_];
__device__ float g_ts [(size_t)MS_ * H_];
#define NTILES_ 33
__device__ uint4 g_wimg_hi[(size_t)NTILES_ * 2048];
__device__ uint4 g_wimg_lo[(size_t)NTILES_ * 2048];

__device__ __forceinline__ uint32_t smem_u32(const void* p) {
    uint32_t a;
    asm("{ .reg .u64 t; cvta.to.shared.u64 t, %1; cvt.u32.u64 %0, t; }" : "=r"(a) : "l"(p));
    return a;
}
__device__ __forceinline__ uint32_t elect1() {
    uint32_t p;
    asm volatile("{\n\t.reg .pred p;\n\telect.sync _|p, 0xFFFFFFFF;\n\tselp.b32 %0, 1, 0, p;\n\t}" : "=r"(p));
    return p;
}
__device__ __forceinline__ uint32_t tile_off(int r, int c) {
    uint32_t off = (uint32_t)((((r >> 3) + ((c >> 6) << 4)) << 10) + ((r & 7) << 7) + ((c & 63) << 1));
    return off ^ ((off >> 3) & 0x70);
}
__device__ __forceinline__ uint32_t scr_off(int row, int g) {
    return (uint32_t)(row * 512 + (((g ^ row) & 7) << 4) + ((g & 24) << 4));
}
__device__ __forceinline__ void split8(const float* a0, uint4& Hv, uint4& Lv) {
    uint32_t h[4], l[4];
    #pragma unroll
    for (int p = 0; p < 4; p++) {
        float x = a0[2 * p], y = a0[2 * p + 1];
        __nv_bfloat162 hh = __floats2bfloat162_rn(x, y);
        __nv_bfloat162 ll = __floats2bfloat162_rn(x - __bfloat162float(hh.x), y - __bfloat162float(hh.y));
        h[p] = *reinterpret_cast<uint32_t*>(&hh);
        l[p] = *reinterpret_cast<uint32_t*>(&ll);
    }
    Hv = make_uint4(h[0], h[1], h[2], h[3]);
    Lv = make_uint4(l[0], l[1], l[2], l[3]);
}

#if TC_OK
#define MBAR_WAIT(mbar, ph) do { \
    uint32_t _m = (mbar), _p = (ph), _d; \
    asm volatile("{\n\t.reg .pred p;\n\tmbarrier.try_wait.parity.acquire.cta.shared::cta.b64 p, [%1], %2;\n\tselp.b32 %0, 1, 0, p;\n\t}" \
        : "=r"(_d) : "r"(_m), "r"(_p) : "memory"); \
    if (!_d) { \
        asm volatile("{\n\t.reg .pred P1;\n\tWL_%=:\n\tmbarrier.try_wait.parity.acquire.cta.shared::cta.b64 P1, [%0], %1, 0x989680;\n\t@P1 bra.uni WD_%=;\n\tbra.uni WL_%=;\n\tWD_%=:\n\t}" \
            :: "r"(_m), "r"(_p) : "memory"); \
    } \
} while(0)
#define LDTM_X32(r, addr) \
    asm volatile("tcgen05.ld.sync.aligned.32x32b.x32.b32 " \
        "{%0,%1,%2,%3,%4,%5,%6,%7,%8,%9,%10,%11,%12,%13,%14,%15," \
        "%16,%17,%18,%19,%20,%21,%22,%23,%24,%25,%26,%27,%28,%29,%30,%31}, [%32];" \
        : "=r"((r)[0]),"=r"((r)[1]),"=r"((r)[2]),"=r"((r)[3]),"=r"((r)[4]),"=r"((r)[5]),"=r"((r)[6]),"=r"((r)[7]), \
          "=r"((r)[8]),"=r"((r)[9]),"=r"((r)[10]),"=r"((r)[11]),"=r"((r)[12]),"=r"((r)[13]),"=r"((r)[14]),"=r"((r)[15]), \
          "=r"((r)[16]),"=r"((r)[17]),"=r"((r)[18]),"=r"((r)[19]),"=r"((r)[20]),"=r"((r)[21]),"=r"((r)[22]),"=r"((r)[23]), \
          "=r"((r)[24]),"=r"((r)[25]),"=r"((r)[26]),"=r"((r)[27]),"=r"((r)[28]),"=r"((r)[29]),"=r"((r)[30]),"=r"((r)[31]) \
        : "r"(addr))
#define DESC_BASE ((2ULL << 61) | (1ULL << 46) | (64ULL << 32) | (1ULL << 16))
__device__ __forceinline__ uint64_t mk_desc(uint32_t addr) {
    return DESC_BASE | ((uint64_t)(addr >> 4) & 0x3FFF);
}
#define IDESC_ 0x8200490u
__device__ __forceinline__ void mma_ss(uint32_t d, uint64_t a, uint64_t b, uint32_t en) {
    asm volatile(
        "{\n\t.reg .pred p;\n\tsetp.ne.u32 p, %5, 0;\n\t"
        "tcgen05.mma.cta_group::1.kind::f16 [%0], %1, %2, %3, {%4, %4, %4, %4}, p;\n\t}"
        :: "r"(d), "l"(a), "l"(b), "r"(IDESC_), "r"(0u), "r"(en) : "memory");
}
#endif

// ---------------- weight prep ----------------
struct PrepArgs { const float *proj, *Wq, *Wk, *Wv, *Wo, *W1, *W2; };
__global__ __launch_bounds__(256) void prep_kernel(PrepArgs a) {
    const int t = blockIdx.x, tid = threadIdx.x;
    const float* src; int ldn = 128, k0 = 0, n0 = 0;
    if (t == 0) { src = a.proj; }
    else {
        int i = (t - 1) >> 3, j = (t - 1) & 7;
        const int HH = H_ * H_, HF = H_ * FF_;
        switch (j) {
            case 0: src = a.Wq + i * HH; break;
            case 1: src = a.Wk + i * HH; break;
            case 2: src = a.Wv + i * HH; break;
            case 3: src = a.Wo + i * HH; break;
            case 4: src = a.W1 + i * HF; ldn = 256; break;
            case 5: src = a.W1 + i * HF; ldn = 256; n0 = 128; break;
            case 6: src = a.W2 + i * HF; break;
            default: src = a.W2 + i * HF; k0 = 128; break;
        }
    }
    char* dh = (char*)(g_wimg_hi + (size_t)t * 2048);
    char* dl = (char*)(g_wimg_lo + (size_t)t * 2048);
    for (int g = tid; g < 2048; g += 256) {
        int n = g >> 4, kg = (g & 15) << 3;
        float v[8];
        #pragma unroll
        for (int d = 0; d < 8; d++) v[d] = src[(size_t)(k0 + kg + d) * ldn + n0 + n];
        uint4 Hv, Lv; split8(v, Hv, Lv);
        uint32_t o = tile_off(n, kg);
        *(uint4*)(dh + o) = Hv; *(uint4*)(dl + o) = Lv;
    }
}

// ---------------- smem layouts ----------------
#define U_BIAS 64
#define U_LNS  1152
#define U_LNB  1664
#define U_PSUM 2176
#define U_PSQ  4224
#define PT_A0   8192
#define PT_A1   73728
#define PT_B    139264
#define PT_SMEM (PT_B + 65536)
#define SM_AHI  8192
#define SM_ALO  40960
#define SM_B    73728
#define SG_SMEM (SM_B + 65536)
#define P2_A    8192
#define P2_B    73728
#define P2_SCR  204800
#define P2_SMEM (P2_SCR + 16384)
#define MG_VM  6272
#define MG_X   8192
#define MG_A   73728
#define MG_B   139264
#define MG_SM  204800

#if TC_OK
// ---- full epilogue (64KB scratch) ----
__device__ __forceinline__ void epi_tile(
    float* v, char* smem, char* scr, int mode, int tile_row0,
    int nh, int rl, int wid, int lid,
    const float* bias_s, const float* res, const float* pos,
    float* C, int ldC, int ncolbase)
{
    const int bcol = nh * 32;
    #pragma unroll
    for (int j = 0; j < 32; j++) v[j] += bias_s[bcol + j];
    if (mode == 1) {
        #pragma unroll
        for (int j = 0; j < 32; j++) v[j] = fmaxf(v[j], 0.f);
    }
    if (mode == 2) {
        #pragma unroll
        for (int rr = 0; rr < 8; rr++) {
            int row = wid * 8 + rr;
            float4 x = *(const float4*)(res + (size_t)(tile_row0 + row) * 128 + lid * 4);
            *(float4*)(scr + scr_off(row, lid)) = x;
        }
        __syncthreads();
        #pragma unroll
        for (int j4 = 0; j4 < 8; j4++) {
            float4 r4 = *(const float4*)(scr + scr_off(rl, (bcol >> 2) + j4));
            v[4*j4+0] += r4.x; v[4*j4+1] += r4.y; v[4*j4+2] += r4.z; v[4*j4+3] += r4.w;
        }
    }
    if (mode >= 2) {
        float s = 0.f, qq = 0.f;
        #pragma unroll
        for (int j = 0; j < 32; j++) { s += v[j]; qq += v[j] * v[j]; }
        ((float*)(smem + U_PSUM))[nh * 128 + rl] = s;
        ((float*)(smem + U_PSQ ))[nh * 128 + rl] = qq;
        __syncthreads();
        float ts = 0.f, tq = 0.f;
        #pragma unroll
        for (int g = 0; g < 4; g++) {
            ts += ((float*)(smem + U_PSUM))[g * 128 + rl];
            tq += ((float*)(smem + U_PSQ ))[g * 128 + rl];
        }
        __syncthreads();
        float mean = ts * (1.f / 128.f);
        float rstd = rsqrtf(tq * (1.f / 128.f) - mean * mean + 1e-5f);
        const float* Ls = (const float*)(smem + U_LNS) + bcol;
        const float* Lb = (const float*)(smem + U_LNB) + bcol;
        #pragma unroll
        for (int j = 0; j < 32; j++) v[j] = (v[j] - mean) * rstd * Ls[j] + Lb[j];
        if (mode == 3) {
            #pragma unroll
            for (int rr = 0; rr < 8; rr++) {
                int row = wid * 8 + rr;
                float4 x = *(const float4*)(pos + (size_t)((tile_row0 + row) & 63) * 128 + lid * 4);
                *(float4*)(scr + scr_off(row, lid)) = x;
            }
            __syncthreads();
            #pragma unroll
            for (int j4 = 0; j4 < 8; j4++) {
                float4 p4 = *(const float4*)(scr + scr_off(rl, (bcol >> 2) + j4));
                v[4*j4+0] = fmaxf(v[4*j4+0], 0.f) + p4.x;
                v[4*j4+1] = fmaxf(v[4*j4+1], 0.f) + p4.y;
                v[4*j4+2] = fmaxf(v[4*j4+2], 0.f) + p4.z;
                v[4*j4+3] = fmaxf(v[4*j4+3], 0.f) + p4.w;
            }
            __syncthreads();
        }
    }
    #pragma unroll
    for (int j4 = 0; j4 < 8; j4++)
        *(float4*)(scr + scr_off(rl, (bcol >> 2) + j4)) =
            make_float4(v[4*j4], v[4*j4+1], v[4*j4+2], v[4*j4+3]);
    __syncthreads();
    #pragma unroll
    for (int rr = 0; rr < 8; rr++) {
        int row = wid * 8 + rr;
        float4 x = *(const float4*)(scr + scr_off(row, lid));
        *(float4*)(C + (size_t)(tile_row0 + row) * ldC + ncolbase + lid * 4) = x;
    }
    __syncthreads();
}

// ---- lite epilogue via 16KB scratch ----
__device__ __forceinline__ void epi_tile_lite(
    float* v, char* scr16, int mode, int tile_row0,
    int nh, int rl, int tid, const float* bias_s,
    float* C, int ldC, int ncolbase)
{
    const int bcol = nh * 32;
    #pragma unroll
    for (int j = 0; j < 32; j++) v[j] += bias_s[bcol + j];
    if (mode == 1) {
        #pragma unroll
        for (int j = 0; j < 32; j++) v[j] = fmaxf(v[j], 0.f);
    }
    #pragma unroll
    for (int p = 0; p < 4; p++) {
        if ((rl >> 5) == p) {
            int r32 = rl & 31;
            #pragma unroll
            for (int j4 = 0; j4 < 8; j4++)
                *(float4*)(scr16 + scr_off(r32, (bcol >> 2) + j4)) =
                    make_float4(v[4*j4], v[4*j4+1], v[4*j4+2], v[4*j4+3]);
        }
        __syncthreads();
        #pragma unroll
        for (int e = 0; e < 2; e++) {
            int id = tid + e * 512;
            int r32 = id >> 5, c = id & 31;
            float4 x = *(const float4*)(scr16 + scr_off(r32, c));
            *(float4*)(C + (size_t)(tile_row0 + p * 32 + r32) * ldC + ncolbase + c * 4) = x;
        }
        __syncthreads();
    }
}
#endif

// ======================= persistent K=128 NT=1 GEMM =======================
__global__ __launch_bounds__(512, 1) void tc_pgemm(
    const float* __restrict__ A, float* __restrict__ C,
    const float* __restrict__ bias, const float* __restrict__ res,
    const float* __restrict__ lns, const float* __restrict__ lnb,
    const float* __restrict__ pos, const int* __restrict__ lengths,
    int ntiles, int mode, int tileB, int padA, int ldC, int n0)
{
#if TC_OK
    extern __shared__ char smem_raw[];
    uint32_t sb0 = smem_u32(smem_raw);
    uint32_t sb = (sb0 + 1023) & ~1023u;
    char* smem = smem_raw + (sb - sb0);
    const int tid = threadIdx.x;
    const int wid = tid >> 5, lid = tid & 31;
    const int nh = wid >> 2;
    const int rl = ((wid & 3) << 5) + lid;

    if (wid == 0)
        asm volatile("tcgen05.alloc.cta_group::1.sync.aligned.shared::cta.b32 [%0], %1;"
                     :: "r"(sb), "r"(256u) : "memory");
    if (tid == 0) {
        asm volatile("mbarrier.init.shared.b64 [%0], %1;" :: "r"(sb + 8), "r"(1u) : "memory");
        asm volatile("mbarrier.init.shared.b64 [%0], %1;" :: "r"(sb + 16), "r"(1u) : "memory");
    }
    if (tid < 128) {
        ((float*)(smem + U_BIAS))[tid] = bias[tid];
        if (mode >= 2) {
            ((float*)(smem + U_LNS))[tid] = lns[tid];
            ((float*)(smem + U_LNB))[tid] = lnb[tid];
        }
    }
    {
        const uint4* sh = g_wimg_hi + (size_t)tileB * 2048;
        const uint4* sl = g_wimg_lo + (size_t)tileB * 2048;
        uint4* dh = (uint4*)(smem + PT_B);
        uint4* dl = (uint4*)(smem + PT_B + 32768);
        #pragma unroll
        for (int u = 0; u < 4; u++) { dh[tid + u*512] = sh[tid + u*512]; dl[tid + u*512] = sl[tid + u*512]; }
    }
    __syncthreads();
    uint32_t tmem;
    asm volatile("ld.shared.b32 %0, [%1];" : "=r"(tmem) : "r"(sb));
    const uint64_t bh = mk_desc(sb + PT_B), bl = mk_desc(sb + PT_B + 32768);
    const float* bias_s = (const float*)(smem + U_BIAS);

    int cnt = 0, prev_it = -1;
    float4 f[8];
    int it = blockIdx.x;
    if (it < ntiles) {
        const float* Ab = A + (size_t)it * 128 * 128;
        #pragma unroll
        for (int u = 0; u < 4; u++) {
            int g = tid + u * 512;
            int r = g >> 4, kg = (g & 15) << 3;
            f[2*u]   = *(const float4*)(Ab + (size_t)r * 128 + kg);
            f[2*u+1] = *(const float4*)(Ab + (size_t)r * 128 + kg + 4);
        }
    }
    for (; it < ntiles; it += gridDim.x, cnt++) {
        const int b = cnt & 1;
        char* abuf = smem + (b ? PT_A1 : PT_A0);
        #pragma unroll
        for (int u = 0; u < 4; u++) {
            int g = tid + u * 512;
            int r = g >> 4, kg = (g & 15) << 3;
            float v8[8];
            v8[0]=f[2*u].x; v8[1]=f[2*u].y; v8[2]=f[2*u].z; v8[3]=f[2*u].w;
            v8[4]=f[2*u+1].x; v8[5]=f[2*u+1].y; v8[6]=f[2*u+1].z; v8[7]=f[2*u+1].w;
            if (padA) {
                int grow = it * 128 + r;
                if ((grow & 63) >= lengths[grow >> 6]) {
                    #pragma unroll
                    for (int d = 0; d < 8; d++) v8[d] = -1.f;
                }
            }
            uint4 Hv, Lv; split8(v8, Hv, Lv);
            uint32_t o = tile_off(r, kg);
            *(uint4*)(abuf + o) = Hv;
            *(uint4*)(abuf + 32768 + o) = Lv;
        }
        __syncthreads();
        if (wid == 0 && elect1()) {
            asm volatile("fence.proxy.async.shared::cta;" ::: "memory");
            asm volatile("tcgen05.fence::after_thread_sync;" ::: "memory");
            uint64_t ah = mk_desc(sb + (b ? PT_A1 : PT_A0));
            uint64_t al = mk_desc(sb + (b ? PT_A1 : PT_A0) + 32768);
            uint32_t d = tmem + b * 128;
            #pragma unroll
            for (int s = 0; s < 8; s++) {
                uint64_t doff = (uint64_t)(((s >> 2) << 10) + ((s & 3) << 1));
                mma_ss(d, ah + doff, bh + doff, s > 0 ? 1u : 0u);
                mma_ss(d, ah + doff, bl + doff, 1u);
                mma_ss(d, al + doff, bh + doff, 1u);
            }
            asm volatile("tcgen05.commit.cta_group::1.mbarrier::arrive::one.shared::cluster.b64 [%0];"
                         :: "r"(sb + 8 + b * 8) : "memory");
        }
        {
            int nit = it + gridDim.x;
            if (nit < ntiles) {
                const float* Ab2 = A + (size_t)nit * 128 * 128;
                #pragma unroll
                for (int u = 0; u < 4; u++) {
                    int g = tid + u * 512;
                    int r = g >> 4, kg = (g & 15) << 3;
                    f[2*u]   = *(const float4*)(Ab2 + (size_t)r * 128 + kg);
                    f[2*u+1] = *(const float4*)(Ab2 + (size_t)r * 128 + kg + 4);
                }
            }
        }
        if (cnt > 0) {
            int pc = cnt - 1, pb = pc & 1;
            MBAR_WAIT(sb + 8 + pb * 8, (pc >> 1) & 1);
            asm volatile("tcgen05.fence::after_thread_sync;" ::: "memory");
            float v[32]; uint32_t vr[32];
            LDTM_X32(vr, tmem + pb * 128 + nh * 32);
            asm volatile("tcgen05.wait::ld.sync.aligned;" ::: "memory");
            #pragma unroll
            for (int j = 0; j < 32; j++) v[j] = __uint_as_float(vr[j]);
            asm volatile("tcgen05.fence::before_thread_sync;" ::: "memory");
            epi_tile(v, smem, smem + (pb ? PT_A1 : PT_A0), mode, prev_it * 128, nh, rl, wid, lid,
                     bias_s, res, pos, C, ldC, n0);
        }
        prev_it = it;
    }
    if (cnt > 0) {
        int pc = cnt - 1, pb = pc & 1;
        MBAR_WAIT(sb + 8 + pb * 8, (pc >> 1) & 1);
        asm volatile("tcgen05.fence::after_thread_sync;" ::: "memory");
        float v[32]; uint32_t vr[32];
        LDTM_X32(vr, tmem + pb * 128 + nh * 32);
        asm volatile("tcgen05.wait::ld.sync.aligned;" ::: "memory");
        #pragma unroll
        for (int j = 0; j < 32; j++) v[j] = __uint_as_float(vr[j]);
        asm volatile("tcgen05.fence::before_thread_sync;" ::: "memory");
        epi_tile(v, smem, smem + (pb ? PT_A0 : PT_A1), mode, prev_it * 128, nh, rl, wid, lid,
                 bias_s, res, pos, C, ldC, n0);
    }
    __syncthreads();
    if (tid == 0) {
        asm volatile("mbarrier.inval.shared.b64 [%0];" :: "r"(sb + 8) : "memory");
        asm volatile("mbarrier.inval.shared.b64 [%0];" :: "r"(sb + 16) : "memory");
    }
    __syncthreads();
    if (wid == 0) {
        asm volatile("tcgen05.relinquish_alloc_permit.cta_group::1.sync.aligned;");
        asm volatile("tcgen05.dealloc.cta_group::1.sync.aligned.b32 %0, %1;" :: "r"(tmem), "r"(256u));
    }
#endif
}

// ============== persistent NT=2 fused GEMM ===========
__global__ __launch_bounds__(512, 1) void tc_pgemm2(
    const float* __restrict__ A, float* __restrict__ C,
    const float* __restrict__ b0p, const float* __restrict__ b1p,
    int ntiles, int mode, int tileB)
{
#if TC_OK
    extern __shared__ char smem_raw[];
    uint32_t sb0 = smem_u32(smem_raw);
    uint32_t sb = (sb0 + 1023) & ~1023u;
    char* smem = smem_raw + (sb - sb0);
    const int tid = threadIdx.x;
    const int wid = tid >> 5, lid = tid & 31;
    const int nh = wid >> 2;
    const int rl = ((wid & 3) << 5) + lid;

    if (wid == 0)
        asm volatile("tcgen05.alloc.cta_group::1.sync.aligned.shared::cta.b32 [%0], %1;"
                     :: "r"(sb), "r"(512u) : "memory");
    if (tid == 0) {
        asm volatile("mbarrier.init.shared.b64 [%0], %1;" :: "r"(sb + 8), "r"(1u) : "memory");
        asm volatile("mbarrier.init.shared.b64 [%0], %1;" :: "r"(sb + 16), "r"(1u) : "memory");
    }
    if (tid < 128) ((float*)(smem + U_BIAS))[tid] = b0p[tid];
    else if (tid < 256) ((float*)(smem + U_BIAS))[tid] = b1p[tid - 128];
    for (int nt = 0; nt < 2; nt++) {
        const uint4* sh = g_wimg_hi + (size_t)(tileB + nt) * 2048;
        const uint4* sl = g_wimg_lo + (size_t)(tileB + nt) * 2048;
        uint4* dh = (uint4*)(smem + P2_B + nt * 65536);
        uint4* dl = (uint4*)(smem + P2_B + nt * 65536 + 32768);
        #pragma unroll
        for (int u = 0; u < 4; u++) { dh[tid + u*512] = sh[tid + u*512]; dl[tid + u*512] = sl[tid + u*512]; }
    }
    __syncthreads();
    uint32_t tmem;
    asm volatile("ld.shared.b32 %0, [%1];" : "=r"(tmem) : "r"(sb));
    const float* bias_s = (const float*)(smem + U_BIAS);
    char* scr16 = smem + P2_SCR;

    int cnt = 0, prev_it = -1;
    float4 f[8];
    int it = blockIdx.x;
    if (it < ntiles) {
        const float* Ab = A + (size_t)it * 128 * 128;
        #pragma unroll
        for (int u = 0; u < 4; u++) {
            int g = tid + u * 512;
            int r = g >> 4, kg = (g & 15) << 3;
            f[2*u]   = *(const float4*)(Ab + (size_t)r * 128 + kg);
            f[2*u+1] = *(const float4*)(Ab + (size_t)r * 128 + kg + 4);
        }
    }
    for (; it < ntiles; it += gridDim.x, cnt++) {
        const int b = cnt & 1;
        if (cnt > 0) {
            int pc = cnt - 1;
            MBAR_WAIT(sb + 8 + (pc & 1) * 8, (pc >> 1) & 1);
        }
        #pragma unroll
        for (int u = 0; u < 4; u++) {
            int g = tid + u * 512;
            int r = g >> 4, kg = (g & 15) << 3;
            float v8[8];
            v8[0]=f[2*u].x; v8[1]=f[2*u].y; v8[2]=f[2*u].z; v8[3]=f[2*u].w;
            v8[4]=f[2*u+1].x; v8[5]=f[2*u+1].y; v8[6]=f[2*u+1].z; v8[7]=f[2*u+1].w;
            uint4 Hv, Lv; split8(v8, Hv, Lv);
            uint32_t o = tile_off(r, kg);
            *(uint4*)(smem + P2_A + o) = Hv;
            *(uint4*)(smem + P2_A + 32768 + o) = Lv;
        }
        __syncthreads();
        if (wid == 0 && elect1()) {
            asm volatile("fence.proxy.async.shared::cta;" ::: "memory");
            asm volatile("tcgen05.fence::after_thread_sync;" ::: "memory");
            uint64_t ah = mk_desc(sb + P2_A), al = mk_desc(sb + P2_A + 32768);
            #pragma unroll
            for (int nt = 0; nt < 2; nt++) {
                uint64_t bhd = mk_desc(sb + P2_B + nt * 65536);
                uint64_t bld = mk_desc(sb + P2_B + nt * 65536 + 32768);
                uint32_t d = tmem + b * 256 + nt * 128;
                #pragma unroll
                for (int s = 0; s < 8; s++) {
                    uint64_t doff = (uint64_t)(((s >> 2) << 10) + ((s & 3) << 1));
                    mma_ss(d, ah + doff, bhd + doff, s > 0 ? 1u : 0u);
                    mma_ss(d, ah + doff, bld + doff, 1u);
                    mma_ss(d, al + doff, bhd + doff, 1u);
                }
            }
            asm volatile("tcgen05.commit.cta_group::1.mbarrier::arrive::one.shared::cluster.b64 [%0];"
                         :: "r"(sb + 8 + b * 8) : "memory");
        }
        {
            int nit = it + gridDim.x;
            if (nit < ntiles) {
                const float* Ab2 = A + (size_t)nit * 128 * 128;
                #pragma unroll
                for (int u = 0; u < 4; u++) {
                    int g = tid + u * 512;
                    int r = g >> 4, kg = (g & 15) << 3;
                    f[2*u]   = *(const float4*)(Ab2 + (size_t)r * 128 + kg);
                    f[2*u+1] = *(const float4*)(Ab2 + (size_t)r * 128 + kg + 4);
                }
            }
        }
        if (cnt > 0) {
            int pb = (cnt - 1) & 1;
            asm volatile("tcgen05.fence::after_thread_sync;" ::: "memory");
            #pragma unroll
            for (int nt = 0; nt < 2; nt++) {
                float v[32]; uint32_t vr[32];
                LDTM_X32(vr, tmem + pb * 256 + nt * 128 + nh * 32);
                asm volatile("tcgen05.wait::ld.sync.aligned;" ::: "memory");
                #pragma unroll
                for (int j = 0; j < 32; j++) v[j] = __uint_as_float(vr[j]);
                asm volatile("tcgen05.fence::before_thread_sync;" ::: "memory");
                epi_tile_lite(v, scr16, mode, prev_it * 128, nh, rl, tid,
                              bias_s + nt * 128, C, 256, nt * 128);
            }
        }
        prev_it = it;
    }
    if (cnt > 0) {
        int pc = cnt - 1, pb = pc & 1;
        MBAR_WAIT(sb + 8 + pb * 8, (pc >> 1) & 1);
        asm volatile("tcgen05.fence::after_thread_sync;" ::: "memory");
        #pragma unroll
        for (int nt = 0; nt < 2; nt++) {
            float v[32]; uint32_t vr[32];
            LDTM_X32(vr, tmem + pb * 256 + nt * 128 + nh * 32);
            asm volatile("tcgen05.wait::ld.sync.aligned;" ::: "memory");
            #pragma unroll
            for (int j = 0; j < 32; j++) v[j] = __uint_as_float(vr[j]);
            asm volatile("tcgen05.fence::before_thread_sync;" ::: "memory");
            epi_tile_lite(v, scr16, mode, prev_it * 128, nh, rl, tid,
                          bias_s + nt * 128, C, 256, nt * 128);
        }
    }
    __syncthreads();
    if (tid == 0) {
        asm volatile("mbarrier.inval.shared.b64 [%0];" :: "r"(sb + 8) : "memory");
        asm volatile("mbarrier.inval.shared.b64 [%0];" :: "r"(sb + 16) : "memory");
    }
    __syncthreads();
    if (wid == 0) {
        asm volatile("tcgen05.relinquish_alloc_permit.cta_group::1.sync.aligned;");
        asm volatile("tcgen05.dealloc.cta_group::1.sync.aligned.b32 %0, %1;" :: "r"(tmem), "r"(512u));
    }
#endif
}

// ======== generic GEMM (2D grid) ======
__global__ __launch_bounds__(512, 1) void tc_gemm(
    const float* __restrict__ A, float* __restrict__ C,
    const float* __restrict__ bias0,
    const float* __restrict__ res, const float* __restrict__ lns,
    const float* __restrict__ lnb,
    int KC, int NT, int mode, int tile0)
{
#if TC_OK
    extern __shared__ char smem_raw[];
    uint32_t sb0 = smem_u32(smem_raw);
    uint32_t sb = (sb0 + 1023) & ~1023u;
    char* smem = smem_raw + (sb - sb0);
    const int tid = threadIdx.x;
    const int wid = tid >> 5, lid = tid & 31;
    const int m0 = blockIdx.x * 128;
    const int nt = blockIdx.y;
    const int Ktot = KC * 128;
    const int N = NT * 128;
    const int nh = wid >> 2;
    const int rl = ((wid & 3) << 5) + lid;

    if (wid == 0)
        asm volatile("tcgen05.alloc.cta_group::1.sync.aligned.shared::cta.b32 [%0], %1;"
                     :: "r"(sb), "r"(128u) : "memory");
    if (tid == 0)
        asm volatile("mbarrier.init.shared.b64 [%0], %1;" :: "r"(sb + 8), "r"(1u) : "memory");
    if (tid < 128) {
        ((float*)(smem + U_BIAS))[tid] = bias0[nt * 128 + tid];
        if (mode >= 2) {
            ((float*)(smem + U_LNS))[tid] = lns[tid];
            ((float*)(smem + U_LNB))[tid] = lnb[tid];
        }
    }
    __syncthreads();
    uint32_t tmem;
    asm volatile("ld.shared.b32 %0, [%1];" : "=r"(tmem) : "r"(sb));

    for (int kc = 0; kc < KC; kc++) {
        if (kc > 0) MBAR_WAIT(sb + 8, (kc - 1) & 1);
        const float* Ab = A + (size_t)m0 * Ktot + kc * 128;
        float4 f[8];
        #pragma unroll
        for (int u = 0; u < 4; u++) {
            int g = tid + u * 512;
            int r = g >> 4, kg = (g & 15) << 3;
            f[2*u]   = *(const float4*)(Ab + (size_t)r * Ktot + kg);
            f[2*u+1] = *(const float4*)(Ab + (size_t)r * Ktot + kg + 4);
        }
        #pragma unroll
        for (int u = 0; u < 4; u++) {
            int g = tid + u * 512;
            int r = g >> 4, kg = (g & 15) << 3;
            float v8[8];
            v8[0]=f[2*u].x; v8[1]=f[2*u].y; v8[2]=f[2*u].z; v8[3]=f[2*u].w;
            v8[4]=f[2*u+1].x; v8[5]=f[2*u+1].y; v8[6]=f[2*u+1].z; v8[7]=f[2*u+1].w;
            uint4 Hv, Lv; split8(v8, Hv, Lv);
            uint32_t o = tile_off(r, kg);
            *(uint4*)(smem + SM_AHI + o) = Hv;
            *(uint4*)(smem + SM_ALO + o) = Lv;
        }
        {
            int tI = tile0 + kc * NT + nt;
            const uint4* sh = g_wimg_hi + (size_t)tI * 2048;
            const uint4* sl = g_wimg_lo + (size_t)tI * 2048;
            uint4* dh = (uint4*)(smem + SM_B);
            uint4* dl = (uint4*)(smem + SM_B + 32768);
            #pragma unroll
            for (int u = 0; u < 4; u++) { dh[tid + u*512] = sh[tid + u*512]; dl[tid + u*512] = sl[tid + u*512]; }
        }
        __syncthreads();
        if (wid == 0 && elect1()) {
            asm volatile("fence.proxy.async.shared::cta;" ::: "memory");
            uint64_t ah = mk_desc(sb + SM_AHI), al = mk_desc(sb + SM_ALO);
            uint64_t bhd = mk_desc(sb + SM_B), bld = mk_desc(sb + SM_B + 32768);
            #pragma unroll
            for (int s = 0; s < 8; s++) {
                uint64_t doff = (uint64_t)(((s >> 2) << 10) + ((s & 3) << 1));
                uint32_t first = (kc == 0 && s == 0) ? 0u : 1u;
                mma_ss(tmem, ah + doff, bhd + doff, first);
                mma_ss(tmem, ah + doff, bld + doff, 1u);
                mma_ss(tmem, al + doff, bhd + doff, 1u);
            }
            asm volatile("tcgen05.commit.cta_group::1.mbarrier::arrive::one.shared::cluster.b64 [%0];"
                         :: "r"(sb + 8) : "memory");
        }
    }
    MBAR_WAIT(sb + 8, (KC - 1) & 1);
    asm volatile("tcgen05.fence::after_thread_sync;" ::: "memory");
    {
        float v[32]; uint32_t vr[32];
        LDTM_X32(vr, tmem + nh * 32);
        asm volatile("tcgen05.wait::ld.sync.aligned;" ::: "memory");
        #pragma unroll
        for (int j = 0; j < 32; j++) v[j] = __uint_as_float(vr[j]);
        asm volatile("tcgen05.fence::before_thread_sync;" ::: "memory");
        epi_tile(v, smem, smem + SM_AHI, mode, m0, nh, rl, wid, lid,
                 (const float*)(smem + U_BIAS), res, nullptr, C, N, nt * 128);
    }
    __syncthreads();
    if (tid == 0)
        asm volatile("mbarrier.inval.shared.b64 [%0];" :: "r"(sb + 8) : "memory");
    __syncthreads();
    if (wid == 0) {
        asm volatile("tcgen05.relinquish_alloc_permit.cta_group::1.sync.aligned;");
        asm volatile("tcgen05.dealloc.cta_group::1.sync.aligned.b32 %0, %1;" :: "r"(tmem), "r"(128u));
    }
#endif
}

// --------- temporal attention (block0) ----
#define ROWF 33
__global__ __launch_bounds__(512) void attn_seq_kernel(
    const float* __restrict__ Q, const float* __restrict__ Km,
    const float* __restrict__ Vm, float* __restrict__ O,
    const int* __restrict__ lengths, int ldkv)
{
    extern __shared__ float4 smf[];
    float4* ks4 = smf;
    float4* vs4 = smf + 64 * ROWF;
    float4* qm4 = smf + 2 * 64 * ROWF;
    const int n = blockIdx.x, tid = threadIdx.x;
    const int head = tid >> 6, i = tid & 63;
    const int ldkv4 = ldkv >> 2;
    const float4* Kb = (const float4*)(Km + (size_t)n * T_ * ldkv);
    const float4* Vb = (const float4*)(Vm + (size_t)n * T_ * ldkv);
    const float4* Qb = (const float4*)(Q  + (size_t)n * T_ * H_);
    #pragma unroll
    for (int u = 0; u < 4; u++) {
        int idx = tid + u * 512;
        int r = idx >> 5, c = idx & 31;
        ks4[r * ROWF + c] = Kb[r * ldkv4 + c];
        vs4[r * ROWF + c] = Vb[r * ldkv4 + c];
        qm4[r * ROWF + c] = Qb[r * 32 + c];
    }
    const int len = lengths[n];
    const int myv = (i < len);
    __syncthreads();
    const int c0 = head * 4;
    float4 q0 = qm4[i * ROWF + c0],     q1 = qm4[i * ROWF + c0 + 1],
           q2 = qm4[i * ROWF + c0 + 2], q3 = qm4[i * ROWF + c0 + 3];
    float m = -1e30f, s = 0.f, acc[16];
    #pragma unroll
    for (int d = 0; d < 16; d++) acc[d] = 0.f;
    for (int j = 0; j < len; j++) {
        float sc;
        if (myv) {
            float4 a0 = ks4[j*ROWF+c0], a1 = ks4[j*ROWF+c0+1],
                   a2 = ks4[j*ROWF+c0+2], a3 = ks4[j*ROWF+c0+3];
            float d = a0.x*q0.x + a0.y*q0.y + a0.z*q0.z + a0.w*q0.w
                    + a1.x*q1.x + a1.y*q1.y + a1.z*q1.z + a1.w*q1.w
                    + a2.x*q2.x + a2.y*q2.y + a2.z*q2.z + a2.w*q2.w
                    + a3.x*q3.x + a3.y*q3.y + a3.z*q3.z + a3.w*q3.w;
            sc = d * SCALE_;
        } else sc = -1e9f;
        float w;
        if (sc > m) {
            float c = __expf(m - sc);
            s = s * c + 1.f;
            #pragma unroll
            for (int d = 0; d < 16; d++) acc[d] *= c;
            m = sc; w = 1.f;
        } else { w = __expf(sc - m); s += w; }
        float4 b0 = vs4[j*ROWF+c0], b1 = vs4[j*ROWF+c0+1],
               b2 = vs4[j*ROWF+c0+2], b3 = vs4[j*ROWF+c0+3];
        acc[0]  += w*b0.x; acc[1]  += w*b0.y; acc[2]  += w*b0.z; acc[3]  += w*b0.w;
        acc[4]  += w*b1.x; acc[5]  += w*b1.y; acc[6]  += w*b1.z; acc[7]  += w*b1.w;
        acc[8]  += w*b2.x; acc[9]  += w*b2.y; acc[10] += w*b2.z; acc[11] += w*b2.w;
        acc[12] += w*b3.x; acc[13] += w*b3.y; acc[14] += w*b3.z; acc[15] += w*b3.w;
    }
    if (!myv) {
        for (int j = len; j < T_; j++) {
            s += 1.f;
            float4 b0 = vs4[j*ROWF+c0], b1 = vs4[j*ROWF+c0+1],
                   b2 = vs4[j*ROWF+c0+2], b3 = vs4[j*ROWF+c0+3];
            acc[0]  += b0.x; acc[1]  += b0.y; acc[2]  += b0.z; acc[3]  += b0.w;
            acc[4]  += b1.x; acc[5]  += b1.y; acc[6]  += b1.z; acc[7]  += b1.w;
            acc[8]  += b2.x; acc[9]  += b2.y; acc[10] += b2.z; acc[11] += b2.w;
            acc[12] += b3.x; acc[13] += b3.y; acc[14] += b3.z; acc[15] += b3.w;
        }
    }
    float inv = 1.f / s;
    __syncthreads();
    qm4[i*ROWF+c0]   = make_float4(acc[0]*inv,  acc[1]*inv,  acc[2]*inv,  acc[3]*inv);
    qm4[i*ROWF+c0+1] = make_float4(acc[4]*inv,  acc[5]*inv,  acc[6]*inv,  acc[7]*inv);
    qm4[i*ROWF+c0+2] = make_float4(acc[8]*inv,  acc[9]*inv,  acc[10]*inv, acc[11]*inv);
    qm4[i*ROWF+c0+3] = make_float4(acc[12]*inv, acc[13]*inv, acc[14]*inv, acc[15]*inv);
    __syncthreads();
    float4* Ob = (float4*)(O + (size_t)n * T_ * H_);
    #pragma unroll
    for (int u = 0; u < 4; u++) {
        int idx = tid + u * 512;
        int r = idx >> 5, c = idx & 31;
        Ob[idx] = qm4[r * ROWF + c];
    }
}

__global__ __launch_bounds__(T_) void attn_t0_kernel(
    const float* __restrict__ Qs, const float* __restrict__ Km,
    const float* __restrict__ Vm, float* __restrict__ O,
    const int* __restrict__ lengths, int ldkv)
{
    const int head = blockIdx.x, n = blockIdx.y, j = threadIdx.x;
    __shared__ float sw[T_];
    const int len = lengths[n], coff = head * 16;
    const float* qp = Qs + (size_t)n * H_ + coff;
    const float* kp = Km + ((size_t)n * T_ + j) * ldkv + coff;
    float d = 0.f;
    #pragma unroll
    for (int dd = 0; dd < 16; dd++) d += qp[dd] * kp[dd];
    float sc = (j < len) ? d * SCALE_ : -1e9f;
    sw[j] = sc;
    __syncthreads();
    float m = -1e30f;
    #pragma unroll 8
    for (int jj = 0; jj < T_; jj++) m = fmaxf(m, sw[jj]);
    float w = __expf(sc - m);
    __syncthreads();
    sw[j] = w;
    __syncthreads();
    if (j < 16) {
        float s = 0.f, acc = 0.f;
        for (int jj = 0; jj < T_; jj++) {
            float wj = sw[jj];
            s += wj;
            acc += wj * Vm[((size_t)n * T_ + jj) * ldkv + coff + j];
        }
        O[(size_t)n * H_ + coff + j] = acc / s;
    }
}

__global__ void gather_t0_kernel(const float* __restrict__ X, float* __restrict__ Xg)
{
    int idx = blockIdx.x * blockDim.x + threadIdx.x;
    if (idx >= MS_ * H_) return;
    Xg[idx] = X[((size_t)(idx / H_) * T_) * H_ + (idx % H_)];
}

// ================== MEGA: b1-post + spatial blocks + output ==================
struct MegaArgs {
    const float *xs, *ts; float* outp;
    const float *bq, *bk, *bv, *bo, *b1, *b2, *l1s, *l1b, *l2s, *l2b;
    const int* len;
};
#if TC_OK
__device__ __forceinline__ void mgB(char* sm, int tile, int tid) {
    const uint4* sh = g_wimg_hi + (size_t)tile * 2048;
    const uint4* sl = g_wimg_lo + (size_t)tile * 2048;
    uint4* dh = (uint4*)(sm + MG_B); uint4* dl = (uint4*)(sm + MG_B + 32768);
    #pragma unroll
    for (int u = 0; u < 4; u++) { dh[tid+u*512] = sh[tid+u*512]; dl[tid+u*512] = sl[tid+u*512]; }
}
__device__ __forceinline__ void mgA_X(char* sm, int tid) {
    #pragma unroll
    for (int u = 0; u < 4; u++) {
        int g = tid + u * 512;
        int r = g >> 4, kg = (g & 15) << 3;
        float4 f0 = *(const float4*)(sm + MG_X + scr_off(r, kg >> 2));
        float4 f1 = *(const float4*)(sm + MG_X + scr_off(r, (kg >> 2) + 1));
        float v8[8] = {f0.x,f0.y,f0.z,f0.w,f1.x,f1.y,f1.z,f1.w};
        uint4 H, L; split8(v8, H, L);
        uint32_t o = tile_off(r, kg);
        *(uint4*)(sm + MG_A + o) = H; *(uint4*)(sm + MG_A + 32768 + o) = L;
    }
}
__device__ __forceinline__ void mgA_gm(char* sm, const float* G, int tid) {
    #pragma unroll
    for (int u = 0; u < 4; u++) {
        int g = tid + u * 512;
        int r = g >> 4, kg = (g & 15) << 3;
        float4 f0 = *(const float4*)(G + (size_t)r * 128 + kg);
        float4 f1 = *(const float4*)(G + (size_t)r * 128 + kg + 4);
        float v8[8] = {f0.x,f0.y,f0.z,f0.w,f1.x,f1.y,f1.z,f1.w};
        uint4 H, L; split8(v8, H, L);
        uint32_t o = tile_off(r, kg);
        *(uint4*)(sm + MG_A + o) = H; *(uint4*)(sm + MG_A + 32768 + o) = L;
    }
}
__device__ __forceinline__ void mgA_regs(char* sm, const float* v, int rl, int bc) {
    #pragma unroll
    for (int u = 0; u < 4; u++) {
        uint4 H, L; split8(v + u * 8, H, L);
        uint32_t o = tile_off(rl, bc + u * 8);
        *(uint4*)(sm + MG_A + o) = H; *(uint4*)(sm + MG_A + 32768 + o) = L;
    }
}
__device__ __forceinline__ void mgMMA(uint32_t sb, uint32_t d, int wid, int fresh) {
    if (wid == 0 && elect1()) {
        asm volatile("fence.proxy.async.shared::cta;" ::: "memory");
        asm volatile("tcgen05.fence::after_thread_sync;" ::: "memory");
        uint64_t ah = mk_desc(sb + MG_A), al = mk_desc(sb + MG_A + 32768);
        uint64_t bh = mk_desc(sb + MG_B), bl = mk_desc(sb + MG_B + 32768);
        #pragma unroll
        for (int s = 0; s < 8; s++) {
            uint64_t doff = (uint64_t)(((s >> 2) << 10) + ((s & 3) << 1));
            mma_ss(d, ah + doff, bh + doff, (fresh && s == 0) ? 0u : 1u);
            mma_ss(d, ah + doff, bl + doff, 1u);
            mma_ss(d, al + doff, bh + doff, 1u);
        }
        asm volatile("tcgen05.commit.cta_group::1.mbarrier::arrive::one.shared::cluster.b64 [%0];"
                     :: "r"(sb + 8) : "memory");
    }
}
__device__ __forceinline__ void mgWAIT(uint32_t sb, int& mc) {
    MBAR_WAIT(sb + 8, mc & 1);
    mc++;
    asm volatile("tcgen05.fence::after_thread_sync;" ::: "memory");
}
__device__ __forceinline__ void mgLDTM(uint32_t tmem, int bank, int nh, float* v) {
    uint32_t vr[32];
    LDTM_X32(vr, tmem + bank + nh * 32);
    asm volatile("tcgen05.wait::ld.sync.aligned;" ::: "memory");
    #pragma unroll
    for (int j = 0; j < 32; j++) v[j] = __uint_as_float(vr[j]);
    asm volatile("tcgen05.fence::before_thread_sync;" ::: "memory");
}
__device__ __forceinline__ void mgLN(char* sm, float* v, int nh, int rl,
    const float* bias, const float* ls, const float* lb)
{
    const int bc = nh * 32;
    #pragma unroll
    for (int j = 0; j < 32; j++) v[j] += bias[bc + j];
    #pragma unroll
    for (int j4 = 0; j4 < 8; j4++) {
        float4 r4 = *(const float4*)(sm + MG_X + scr_off(rl, (bc >> 2) + j4));
        v[4*j4+0] += r4.x; v[4*j4+1] += r4.y; v[4*j4+2] += r4.z; v[4*j4+3] += r4.w;
    }
    float s = 0.f, qq = 0.f;
    #pragma unroll
    for (int j = 0; j < 32; j++) { s += v[j]; qq += v[j] * v[j]; }
    ((float*)(sm + U_PSUM))[nh * 128 + rl] = s;
    ((float*)(sm + U_PSQ ))[nh * 128 + rl] = qq;
    __syncthreads();
    float ts = 0.f, tq = 0.f;
    #pragma unroll
    for (int g = 0; g < 4; g++) {
        ts += ((float*)(sm + U_PSUM))[g * 128 + rl];
        tq += ((float*)(sm + U_PSQ ))[g * 128 + rl];
    }
    __syncthreads();
    float mean = ts * (1.f / 128.f);
    float rstd = rsqrtf(tq * (1.f / 128.f) - mean * mean + 1e-5f);
    #pragma unroll
    for (int j = 0; j < 32; j++)
        v[j] = (v[j] - mean) * rstd * ls[bc + j] + lb[bc + j];
    #pragma unroll
    for (int j4 = 0; j4 < 8; j4++)
        *(float4*)(sm + MG_X + scr_off(rl, (bc >> 2) + j4)) =
            make_float4(v[4*j4], v[4*j4+1], v[4*j4+2], v[4*j4+3]);
    __syncthreads();
}
__device__ __forceinline__ void mgFFN(char* sm, uint32_t sb, uint32_t tmem, int& mc,
    int tid, int wid, int nh, int rl, int t0,
    const float* b1p, const float* b2p, const float* ls, const float* lb)
{
    float v[32];
    const int bc = nh * 32;
    #pragma unroll 1
    for (int hf = 0; hf < 2; hf++) {
        mgA_X(sm, tid); mgB(sm, t0 + 4 + hf, tid); __syncthreads();
        mgMMA(sb, tmem + 128, wid, 1); mgWAIT(sb, mc);
        mgLDTM(tmem, 128, nh, v);
        #pragma unroll
        for (int j = 0; j < 32; j++) v[j] = fmaxf(v[j] + b1p[hf * 128 + bc + j], 0.f);
        mgA_regs(sm, v, rl, bc); mgB(sm, t0 + 6 + hf, tid); __syncthreads();
        mgMMA(sb, tmem + 256, wid, hf == 0); mgWAIT(sb, mc);
    }
    mgLDTM(tmem, 256, nh, v);
    mgLN(sm, v, nh, rl, b2p, ls, lb);
}
__device__ __forceinline__ void mgATT(char* sm, const float* q, float* o, int nh, int rl) {
    const int* vm = (const int*)(sm + MG_VM);
    const int myv = vm[rl];
    #pragma unroll 1
    for (int h2 = 0; h2 < 2; h2++) {
        const int h = nh * 2 + h2;
        const float* qh = q + h2 * 16;
        float m = -1e30f, s = 0.f, acc[16];
        #pragma unroll
        for (int d = 0; d < 16; d++) acc[d] = 0.f;
        for (int j = 0; j < 128; j++) {
            int vj = vm[j];
            float sc;
            if (myv && vj) {
                float4 a0 = *(const float4*)(sm + MG_A + scr_off(j, h * 4));
                float4 a1 = *(const float4*)(sm + MG_A + scr_off(j, h * 4 + 1));
                float4 a2 = *(const float4*)(sm + MG_A + scr_off(j, h * 4 + 2));
                float4 a3 = *(const float4*)(sm + MG_A + scr_off(j, h * 4 + 3));
                float d = a0.x*qh[0] + a0.y*qh[1] + a0.z*qh[2] + a0.w*qh[3]
                        + a1.x*qh[4] + a1.y*qh[5] + a1.z*qh[6] + a1.w*qh[7]
                        + a2.x*qh[8] + a2.y*qh[9] + a2.z*qh[10] + a2.w*qh[11]
                        + a3.x*qh[12] + a3.y*qh[13] + a3.z*qh[14] + a3.w*qh[15];
                sc = d * SCALE_;
            } else if (!myv && !vj) sc = -1e9f;   // contributes uniformly below
            else if (myv && !vj) continue;        // valid query skips invalid key
            else sc = -1e9f;                      // invalid query, valid key
            float w;
            if (sc > m) {
                float c = __expf(m - sc);
                s = s * c + 1.f;
                #pragma unroll
                for (int d = 0; d < 16; d++) acc[d] *= c;
                m = sc; w = 1.f;
            } else { w = __expf(sc - m); s += w; }
            float4 b0 = *(const float4*)(sm + MG_B + scr_off(j, h * 4));
            float4 b1 = *(const float4*)(sm + MG_B + scr_off(j, h * 4 + 1));
            float4 b2 = *(const float4*)(sm + MG_B + scr_off(j, h * 4 + 2));
            float4 b3 = *(const float4*)(sm + MG_B + scr_off(j, h * 4 + 3));
            acc[0]  += w*b0.x; acc[1]  += w*b0.y; acc[2]  += w*b0.z; acc[3]  += w*b0.w;
            acc[4]  += w*b1.x; acc[5]  += w*b1.y; acc[6]  += w*b1.z; acc[7]  += w*b1.w;
            acc[8]  += w*b2.x; acc[9]  += w*b2.y; acc[10] += w*b2.z; acc[11] += w*b2.w;
            acc[12] += w*b3.x; acc[13] += w*b3.y; acc[14] += w*b3.z; acc[15] += w*b3.w;
        }
        float inv = 1.f / s;
        #pragma unroll
        for (int d = 0; d < 16; d++) o[h2 * 16 + d] = acc[d] * inv;
    }
}
#endif

__global__ __launch_bounds__(512, 1) void mega_kernel(MegaArgs a)
{
#if TC_OK
    extern __shared__ char smraw[];
    uint32_t sb0 = smem_u32(smraw);
    uint32_t sb = (sb0 + 1023) & ~1023u;
    char* sm = smraw + (sb - sb0);
    const int b = blockIdx.x, tid = threadIdx.x;
    const int wid = tid >> 5, lid = tid & 31;
    const int nh = wid >> 2;
    const int rl = ((wid & 3) << 5) + lid;
    const int bc = nh * 32;

    if (wid == 0)
        asm volatile("tcgen05.alloc.cta_group::1.sync.aligned.shared::cta.b32 [%0], %1;"
                     :: "r"(sb), "r"(512u) : "memory");
    if (tid == 0)
        asm volatile("mbarrier.init.shared.b64 [%0], %1;" :: "r"(sb + 8), "r"(1u) : "memory");
    {
        const float4* src = (const float4*)(a.xs + (size_t)b * 16384);
        #pragma unroll
        for (int u = 0; u < 8; u++) {
            int idx = tid + u * 512;
            *(float4*)(sm + MG_X + scr_off(idx >> 5, idx & 31)) = src[idx];
        }
        if (tid < 128) ((int*)(sm + MG_VM))[tid] = (a.len[b * 128 + tid] > 0) ? 1 : 0;
    }
    __syncthreads();
    uint32_t tmem;
    asm volatile("ld.shared.b32 %0, [%1];" : "=r"(tmem) : "r"(sb));
    int mc = 0;
    float v[32], qr[32], ov[32];

    // ---- b1 post-attention: Wo + LN1, FFN + LN2 ----
    mgA_gm(sm, a.ts + (size_t)b * 16384, tid); mgB(sm, 12, tid); __syncthreads();
    mgMMA(sb, tmem, wid, 1); mgWAIT(sb, mc);
    mgLDTM(tmem, 0, nh, v);
    mgLN(sm, v, nh, rl, a.bo + H_, a.l1s + H_, a.l1b + H_);
    mgFFN(sm, sb, tmem, mc, tid, wid, nh, rl, 9, a.b1 + FF_, a.b2 + H_, a.l2s + H_, a.l2b + H_);

    // ---- spatial blocks 2, 3 ----
    #pragma unroll 1
    for (int L = 2; L < 4; L++) {
        const int t0 = 1 + L * 8;
        mgA_X(sm, tid);
        mgB(sm, t0, tid); __syncthreads();
        mgMMA(sb, tmem, wid, 1); mgWAIT(sb, mc);
        mgB(sm, t0 + 1, tid); __syncthreads();
        mgMMA(sb, tmem + 128, wid, 1); mgWAIT(sb, mc);
        mgB(sm, t0 + 2, tid); __syncthreads();
        mgMMA(sb, tmem + 256, wid, 1); mgWAIT(sb, mc);
        mgLDTM(tmem, 0, nh, qr);
        #pragma unroll
        for (int j = 0; j < 32; j++) qr[j] += a.bq[L * H_ + bc + j];
        mgLDTM(tmem, 128, nh, v);     // K -> fp32 smem over A region
        #pragma unroll
        for (int j4 = 0; j4 < 8; j4++)
            *(float4*)(sm + MG_A + scr_off(rl, (bc >> 2) + j4)) =
                make_float4(v[4*j4]   + a.bk[L*H_+bc+4*j4],
                            v[4*j4+1] + a.bk[L*H_+bc+4*j4+1],
                            v[4*j4+2] + a.bk[L*H_+bc+4*j4+2],
                            v[4*j4+3] + a.bk[L*H_+bc+4*j4+3]);
        mgLDTM(tmem, 256, nh, v);     // V -> fp32 smem over B region
        #pragma unroll
        for (int j4 = 0; j4 < 8; j4++)
            *(float4*)(sm + MG_B + scr_off(rl, (bc >> 2) + j4)) =
                make_float4(v[4*j4]   + a.bv[L*H_+bc+4*j4],
                            v[4*j4+1] + a.bv[L*H_+bc+4*j4+1],
                            v[4*j4+2] + a.bv[L*H_+bc+4*j4+2],
                            v[4*j4+3] + a.bv[L*H_+bc+4*j4+3]);
        __syncthreads();
        mgATT(sm, qr, ov, nh, rl);
        __syncthreads();
        mgA_regs(sm, ov, rl, bc);
        mgB(sm, t0 + 3, tid); __syncthreads();
        mgMMA(sb, tmem, wid, 1); mgWAIT(sb, mc);
        mgLDTM(tmem, 0, nh, v);
        mgLN(sm, v, nh, rl, a.bo + L * H_, a.l1s + L * H_, a.l1b + L * H_);
        mgFFN(sm, sb, tmem, mc, tid, wid, nh, rl, t0,
              a.b1 + L * FF_, a.b2 + L * H_, a.l2s + L * H_, a.l2b + L * H_);
    }

    // ---- final output: rows 0..63 of this tile ----
    {
        float4* dst = (float4*)(a.outp + (size_t)b * 64 * 128);
        #pragma unroll
        for (int u = 0; u < 4; u++) {
            int id = tid + u * 512;    // 0..2047
            dst[id] = *(const float4*)(sm + MG_X + scr_off(id >> 5, id & 31));
        }
    }
    __syncthreads();
    if (tid == 0)
        asm volatile("mbarrier.inval.shared.b64 [%0];" :: "r"(sb + 8) : "memory");
    __syncthreads();
    if (wid == 0) {
        asm volatile("tcgen05.relinquish_alloc_permit.cta_group::1.sync.aligned;");
        asm volatile("tcgen05.dealloc.cta_group::1.sync.aligned.b32 %0, %1;" :: "r"(tmem), "r"(512u));
    }
#endif
}

// ---------------- host ----------------
#define PGRID_ 152
#define ATTN_SMEM (3 * 64 * ROWF * 16)
static void tcP(const float* A, float* C, const float* bias, const float* res,
                const float* lns, const float* lnb, const float* pos, const int* len,
                int ntiles, int mode, int tileB, int padA, int ldC, int n0)
{
    tc_pgemm<<<PGRID_, 512, PT_SMEM + 1024>>>(A, C, bias, res, lns, lnb, pos, len,
                                              ntiles, mode, tileB, padA, ldC, n0);
}

extern "C" void kernel_launch(void* const* d_in, const int* in_sizes, int n_in,
                              void* d_out, int out_size)
{
    const float* poly = (const float*)d_in[0];
    const int*   len  = (const int*)  d_in[1];
    const float* pw   = (const float*)d_in[2];
    const float* pb   = (const float*)d_in[3];
    const float* pls  = (const float*)d_in[4];
    const float* plb  = (const float*)d_in[5];
    const float* pos  = (const float*)d_in[6];
    const float* Wq   = (const float*)d_in[7];
    const float* bq   = (const float*)d_in[8];
    const float* Wk   = (const float*)d_in[9];
    const float* bk   = (const float*)d_in[10];
    const float* Wv   = (const float*)d_in[11];
    const float* bv   = (const float*)d_in[12];
    const float* Wo   = (const float*)d_in[13];
    const float* bo   = (const float*)d_in[14];
    const float* l1s  = (const float*)d_in[15];
    const float* l1b  = (const float*)d_in[16];
    const float* W1   = (const float*)d_in[17];
    const float* b1   = (const float*)d_in[18];
    const float* W2   = (const float*)d_in[19];
    const float* b2   = (const float*)d_in[20];
    const float* l2s  = (const float*)d_in[21];
    const float* l2b  = (const float*)d_in[22];
    float* out = (float*)d_out;

    cudaFuncSetAttribute(tc_gemm, cudaFuncAttributeMaxDynamicSharedMemorySize, SG_SMEM + 1024);
    cudaFuncSetAttribute(tc_pgemm, cudaFuncAttributeMaxDynamicSharedMemorySize, PT_SMEM + 1024);
    cudaFuncSetAttribute(tc_pgemm2, cudaFuncAttributeMaxDynamicSharedMemorySize, P2_SMEM + 1024);
    cudaFuncSetAttribute(mega_kernel, cudaFuncAttributeMaxDynamicSharedMemorySize, MG_SM + 1024);
    cudaFuncSetAttribute(attn_seq_kernel, cudaFuncAttributeMaxDynamicSharedMemorySize, ATTN_SMEM);

    float *x, *tmp, *q, *hb, *xs, *qs, *ts;
    cudaGetSymbolAddress((void**)&x, g_x);   cudaGetSymbolAddress((void**)&tmp, g_tmp);
    cudaGetSymbolAddress((void**)&q, g_q);   cudaGetSymbolAddress((void**)&hb, g_h);
    cudaGetSymbolAddress((void**)&xs, g_xs); cudaGetSymbolAddress((void**)&qs, g_qs);
    cudaGetSymbolAddress((void**)&ts, g_ts);

    const int NTIL0 = M0_ / 128;

    PrepArgs pa{pw, Wq, Wk, Wv, Wo, W1, W2};
    prep_kernel<<<NTILES_, 256>>>(pa);

    // embed
    tcP(poly, x, pb, nullptr, pls, plb, pos, len, NTIL0, 3, 0, 1, 128, 0);
    // block 0
    tcP(x, q, bq, nullptr, nullptr, nullptr, nullptr, nullptr, NTIL0, 0, 1, 0, 128, 0);
    tc_pgemm2<<<PGRID_, 512, P2_SMEM + 1024>>>(x, hb, bk, bv, NTIL0, 0, 2);
    attn_seq_kernel<<<B_ * S_, 512, ATTN_SMEM>>>(q, hb, hb + 128, tmp, len, 256);
    tcP(tmp, x, bo, x, l1s, l1b, nullptr, nullptr, NTIL0, 2, 4, 0, 128, 0);
    tc_pgemm2<<<PGRID_, 512, P2_SMEM + 1024>>>(x, hb, b1, b1 + 128, NTIL0, 1, 5);
    tc_gemm<<<dim3(M0_ / 128, 1), 512, SG_SMEM + 1024>>>(hb, x, b2, x, l2s, l2b, 2, 1, 2, 7);
    // block 1 front
    tc_pgemm2<<<PGRID_, 512, P2_SMEM + 1024>>>(x, hb, bk + H_, bv + H_, NTIL0, 0, 10);
    gather_t0_kernel<<<(MS_ * H_ + 255) / 256, 256>>>(x, xs);
    tc_gemm<<<dim3(MS_ / 128, 1), 512, SG_SMEM + 1024>>>(xs, qs, bq + H_, nullptr, nullptr, nullptr, 1, 1, 0, 9);
    attn_t0_kernel<<<dim3(8, MS_), T_>>>(qs, hb, hb + 128, ts, len, 256);
    // back half: mega
    MegaArgs ma{xs, ts, out, bq, bk, bv, bo, b1, b2, l1s, l1b, l2s, l2b, len};
    mega_kernel<<<B_, 512, MG_SM + 1024>>>(ma);
    (void)in_sizes; (void)n_in; (void)out_size;
}

// round 14
// speedup vs baseline: 1.1537x; 1.1537x over previous
#include <cuda_runtime.h>
#include <cuda_bf16.h>
#include <cstdint>

#define B_  16
#define S_  128
#define T_  64
#define H_  128
#define NH_ 8
#define DH_ 16
#define DHP 20
#define FF_ 256
#define NL_ 4
#define M0_ (B_*S_*T_)
#define MS_ (B_*S_)
#define SCALE_ 0.25f

#if defined(__CUDA_ARCH__) && (defined(__CUDA_ARCH_FEAT_SM103_ALL) || \
    defined(__CUDA_ARCH_FEAT_SM100_ALL) || defined(__CUDA_ARCH_SPECIFIC__) || \
    defined(__CUDA_ARCH_FAMILY_SPECIFIC__))
#define TC_OK 1
#else
#define TC_OK 0
#endif

// ---------------- device scratch ----------------
__device__ float g_x  [(size_t)M0_ * H_];
__device__ float g_tmp[(size_t)M0_ * H_];
__device__ float g_q  [(size_t)M0_ * H_];
__device__ float g_h  [(size_t)M0_ * FF_];   // also hosts fused KV [M0,256]
__device__ float g_xs [(size_t)MS_ * H_];
__device__ float g_qs [(size_t)MS_ * H_];
__device__ float g_qkv[(size_t)MS_ * 384];
__device__ float g_ts [(size_t)MS_ * H_];
__device__ float g_hs [(size_t)MS_ * FF_];
#define NTILES_ 33
__device__ uint4 g_wimg_hi[(size_t)NTILES_ * 2048];
__device__ uint4 g_wimg_lo[(size_t)NTILES_ * 2048];

// ---------------- helpers ----------------
__device__ __forceinline__ uint32_t smem_u32(const void* p) {
    uint32_t a;
    asm("{ .reg .u64 t; cvta.to.shared.u64 t, %1; cvt.u32.u64 %0, t; }" : "=r"(a) : "l"(p));
    return a;
}
__device__ __forceinline__ uint32_t elect1() {
    uint32_t p;
    asm volatile("{\n\t.reg .pred p;\n\telect.sync _|p, 0xFFFFFFFF;\n\tselp.b32 %0, 1, 0, p;\n\t}" : "=r"(p));
    return p;
}
__device__ __forceinline__ uint32_t tile_off(int r, int c) {
    uint32_t off = (uint32_t)((((r >> 3) + ((c >> 6) << 4)) << 10) + ((r & 7) << 7) + ((c & 63) << 1));
    return off ^ ((off >> 3) & 0x70);
}
// scratch swizzle on 16B granules; rows of 512B
__device__ __forceinline__ uint32_t scr_off(int row, int g) {
    return (uint32_t)(row * 512 + (((g ^ row) & 7) << 4) + ((g & 24) << 4));
}
__device__ __forceinline__ void split8(const float* a0, uint4& Hv, uint4& Lv) {
    uint32_t h[4], l[4];
    #pragma unroll
    for (int p = 0; p < 4; p++) {
        float x = a0[2 * p], y = a0[2 * p + 1];
        __nv_bfloat162 hh = __floats2bfloat162_rn(x, y);
        __nv_bfloat162 ll = __floats2bfloat162_rn(x - __bfloat162float(hh.x), y - __bfloat162float(hh.y));
        h[p] = *reinterpret_cast<uint32_t*>(&hh);
        l[p] = *reinterpret_cast<uint32_t*>(&ll);
    }
    Hv = make_uint4(h[0], h[1], h[2], h[3]);
    Lv = make_uint4(l[0], l[1], l[2], l[3]);
}

#if TC_OK
#define MBAR_WAIT(mbar, ph) do { \
    uint32_t _m = (mbar), _p = (ph), _d; \
    asm volatile("{\n\t.reg .pred p;\n\tmbarrier.try_wait.parity.acquire.cta.shared::cta.b64 p, [%1], %2;\n\tselp.b32 %0, 1, 0, p;\n\t}" \
        : "=r"(_d) : "r"(_m), "r"(_p) : "memory"); \
    if (!_d) { \
        asm volatile("{\n\t.reg .pred P1;\n\tWL_%=:\n\tmbarrier.try_wait.parity.acquire.cta.shared::cta.b64 P1, [%0], %1, 0x989680;\n\t@P1 bra.uni WD_%=;\n\tbra.uni WL_%=;\n\tWD_%=:\n\t}" \
            :: "r"(_m), "r"(_p) : "memory"); \
    } \
} while(0)
#define LDTM_X32(r, addr) \
    asm volatile("tcgen05.ld.sync.aligned.32x32b.x32.b32 " \
        "{%0,%1,%2,%3,%4,%5,%6,%7,%8,%9,%10,%11,%12,%13,%14,%15," \
        "%16,%17,%18,%19,%20,%21,%22,%23,%24,%25,%26,%27,%28,%29,%30,%31}, [%32];" \
        : "=r"((r)[0]),"=r"((r)[1]),"=r"((r)[2]),"=r"((r)[3]),"=r"((r)[4]),"=r"((r)[5]),"=r"((r)[6]),"=r"((r)[7]), \
          "=r"((r)[8]),"=r"((r)[9]),"=r"((r)[10]),"=r"((r)[11]),"=r"((r)[12]),"=r"((r)[13]),"=r"((r)[14]),"=r"((r)[15]), \
          "=r"((r)[16]),"=r"((r)[17]),"=r"((r)[18]),"=r"((r)[19]),"=r"((r)[20]),"=r"((r)[21]),"=r"((r)[22]),"=r"((r)[23]), \
          "=r"((r)[24]),"=r"((r)[25]),"=r"((r)[26]),"=r"((r)[27]),"=r"((r)[28]),"=r"((r)[29]),"=r"((r)[30]),"=r"((r)[31]) \
        : "r"(addr))
#define DESC_BASE ((2ULL << 61) | (1ULL << 46) | (64ULL << 32) | (1ULL << 16))
__device__ __forceinline__ uint64_t mk_desc(uint32_t addr) {
    return DESC_BASE | ((uint64_t)(addr >> 4) & 0x3FFF);
}
#define IDESC_ 0x8200490u
__device__ __forceinline__ void mma_ss(uint32_t d, uint64_t a, uint64_t b, uint32_t en) {
    asm volatile(
        "{\n\t.reg .pred p;\n\tsetp.ne.u32 p, %5, 0;\n\t"
        "tcgen05.mma.cta_group::1.kind::f16 [%0], %1, %2, %3, {%4, %4, %4, %4}, p;\n\t}"
        :: "r"(d), "l"(a), "l"(b), "r"(IDESC_), "r"(0u), "r"(en) : "memory");
}
#endif

// ---------------- weight prep ----------------
struct PrepArgs { const float *proj, *Wq, *Wk, *Wv, *Wo, *W1, *W2; };
__global__ __launch_bounds__(256) void prep_kernel(PrepArgs a) {
    const int t = blockIdx.x, tid = threadIdx.x;
    const float* src; int ldn = 128, k0 = 0, n0 = 0;
    if (t == 0) { src = a.proj; }
    else {
        int i = (t - 1) >> 3, j = (t - 1) & 7;
        const int HH = H_ * H_, HF = H_ * FF_;
        switch (j) {
            case 0: src = a.Wq + i * HH; break;
            case 1: src = a.Wk + i * HH; break;
            case 2: src = a.Wv + i * HH; break;
            case 3: src = a.Wo + i * HH; break;
            case 4: src = a.W1 + i * HF; ldn = 256; break;
            case 5: src = a.W1 + i * HF; ldn = 256; n0 = 128; break;
            case 6: src = a.W2 + i * HF; break;
            default: src = a.W2 + i * HF; k0 = 128; break;
        }
    }
    char* dh = (char*)(g_wimg_hi + (size_t)t * 2048);
    char* dl = (char*)(g_wimg_lo + (size_t)t * 2048);
    for (int g = tid; g < 2048; g += 256) {
        int n = g >> 4, kg = (g & 15) << 3;
        float v[8];
        #pragma unroll
        for (int d = 0; d < 8; d++) v[d] = src[(size_t)(k0 + kg + d) * ldn + n0 + n];
        uint4 Hv, Lv; split8(v, Hv, Lv);
        uint32_t o = tile_off(n, kg);
        *(uint4*)(dh + o) = Hv; *(uint4*)(dl + o) = Lv;
    }
}

// ---------------- smem layouts ----------------
#define U_BIAS 64
#define U_LNS  1152
#define U_LNB  1664
#define U_PSUM 2176
#define U_PSQ  4224
#define PT_A0   8192
#define PT_A1   73728
#define PT_B    139264
#define PT_SMEM (PT_B + 65536)
#define SM_AHI  8192
#define SM_ALO  40960
#define SM_B    73728
#define SG_SMEM (SM_B + 65536)
// pgemm2: single A buf + 2 B tiles + 16KB scratch
#define P2_A    8192
#define P2_B    73728
#define P2_SCR  204800
#define P2_SMEM (P2_SCR + 16384)

#if TC_OK
// ---- epilogue on one 128x128 C tile (full-featured, 64KB scratch) ----
__device__ __forceinline__ void epi_tile(
    float* v, char* smem, char* scr, int mode, int tile_row0,
    int nh, int rl, int wid, int lid,
    const float* bias_s, const float* res, const float* pos,
    float* C, int ldC, int ncolbase)
{
    const int bcol = nh * 32;
    #pragma unroll
    for (int j = 0; j < 32; j++) v[j] += bias_s[bcol + j];
    if (mode == 1) {
        #pragma unroll
        for (int j = 0; j < 32; j++) v[j] = fmaxf(v[j], 0.f);
    }
    if (mode == 2) {
        #pragma unroll
        for (int rr = 0; rr < 8; rr++) {
            int row = wid * 8 + rr;
            float4 x = *(const float4*)(res + (size_t)(tile_row0 + row) * 128 + lid * 4);
            *(float4*)(scr + scr_off(row, lid)) = x;
        }
        __syncthreads();
        #pragma unroll
        for (int j4 = 0; j4 < 8; j4++) {
            float4 r4 = *(const float4*)(scr + scr_off(rl, (bcol >> 2) + j4));
            v[4*j4+0] += r4.x; v[4*j4+1] += r4.y; v[4*j4+2] += r4.z; v[4*j4+3] += r4.w;
        }
    }
    if (mode >= 2) {
        float s = 0.f, qq = 0.f;
        #pragma unroll
        for (int j = 0; j < 32; j++) { s += v[j]; qq += v[j] * v[j]; }
        ((float*)(smem + U_PSUM))[nh * 128 + rl] = s;
        ((float*)(smem + U_PSQ ))[nh * 128 + rl] = qq;
        __syncthreads();
        float ts = 0.f, tq = 0.f;
        #pragma unroll
        for (int g = 0; g < 4; g++) {
            ts += ((float*)(smem + U_PSUM))[g * 128 + rl];
            tq += ((float*)(smem + U_PSQ ))[g * 128 + rl];
        }
        __syncthreads();
        float mean = ts * (1.f / 128.f);
        float rstd = rsqrtf(tq * (1.f / 128.f) - mean * mean + 1e-5f);
        const float* Ls = (const float*)(smem + U_LNS) + bcol;
        const float* Lb = (const float*)(smem + U_LNB) + bcol;
        #pragma unroll
        for (int j = 0; j < 32; j++) v[j] = (v[j] - mean) * rstd * Ls[j] + Lb[j];
        if (mode == 3) {
            #pragma unroll
            for (int rr = 0; rr < 8; rr++) {
                int row = wid * 8 + rr;
                float4 x = *(const float4*)(pos + (size_t)((tile_row0 + row) & 63) * 128 + lid * 4);
                *(float4*)(scr + scr_off(row, lid)) = x;
            }
            __syncthreads();
            #pragma unroll
            for (int j4 = 0; j4 < 8; j4++) {
                float4 p4 = *(const float4*)(scr + scr_off(rl, (bcol >> 2) + j4));
                v[4*j4+0] = fmaxf(v[4*j4+0], 0.f) + p4.x;
                v[4*j4+1] = fmaxf(v[4*j4+1], 0.f) + p4.y;
                v[4*j4+2] = fmaxf(v[4*j4+2], 0.f) + p4.z;
                v[4*j4+3] = fmaxf(v[4*j4+3], 0.f) + p4.w;
            }
            __syncthreads();
        }
    }
    #pragma unroll
    for (int j4 = 0; j4 < 8; j4++)
        *(float4*)(scr + scr_off(rl, (bcol >> 2) + j4)) =
            make_float4(v[4*j4], v[4*j4+1], v[4*j4+2], v[4*j4+3]);
    __syncthreads();
    #pragma unroll
    for (int rr = 0; rr < 8; rr++) {
        int row = wid * 8 + rr;
        float4 x = *(const float4*)(scr + scr_off(row, lid));
        *(float4*)(C + (size_t)(tile_row0 + row) * ldC + ncolbase + lid * 4) = x;
    }
    __syncthreads();
}

// ---- lite epilogue via 16KB scratch, 4 row-phases (bias + optional relu) ----
__device__ __forceinline__ void epi_tile_lite(
    float* v, char* scr16, int mode, int tile_row0,
    int nh, int rl, int tid, const float* bias_s,
    float* C, int ldC, int ncolbase)
{
    const int bcol = nh * 32;
    #pragma unroll
    for (int j = 0; j < 32; j++) v[j] += bias_s[bcol + j];
    if (mode == 1) {
        #pragma unroll
        for (int j = 0; j < 32; j++) v[j] = fmaxf(v[j], 0.f);
    }
    #pragma unroll
    for (int p = 0; p < 4; p++) {
        if ((rl >> 5) == p) {
            int r32 = rl & 31;
            #pragma unroll
            for (int j4 = 0; j4 < 8; j4++)
                *(float4*)(scr16 + scr_off(r32, (bcol >> 2) + j4)) =
                    make_float4(v[4*j4], v[4*j4+1], v[4*j4+2], v[4*j4+3]);
        }
        __syncthreads();
        #pragma unroll
        for (int e = 0; e < 2; e++) {
            int id = tid + e * 512;
            int r32 = id >> 5, c = id & 31;
            float4 x = *(const float4*)(scr16 + scr_off(r32, c));
            *(float4*)(C + (size_t)(tile_row0 + p * 32 + r32) * ldC + ncolbase + c * 4) = x;
        }
        __syncthreads();
    }
}
#endif

// ======================= persistent K=128 NT=1 GEMM =======================
__global__ __launch_bounds__(512, 1) void tc_pgemm(
    const float* __restrict__ A, float* __restrict__ C,
    const float* __restrict__ bias, const float* __restrict__ res,
    const float* __restrict__ lns, const float* __restrict__ lnb,
    const float* __restrict__ pos, const int* __restrict__ lengths,
    int ntiles, int mode, int tileB, int padA, int ldC, int n0)
{
#if TC_OK
    extern __shared__ char smem_raw[];
    uint32_t sb0 = smem_u32(smem_raw);
    uint32_t sb = (sb0 + 1023) & ~1023u;
    char* smem = smem_raw + (sb - sb0);
    const int tid = threadIdx.x;
    const int wid = tid >> 5, lid = tid & 31;
    const int nh = wid >> 2;
    const int rl = ((wid & 3) << 5) + lid;

    if (wid == 0)
        asm volatile("tcgen05.alloc.cta_group::1.sync.aligned.shared::cta.b32 [%0], %1;"
                     :: "r"(sb), "r"(256u) : "memory");
    if (tid == 0) {
        asm volatile("mbarrier.init.shared.b64 [%0], %1;" :: "r"(sb + 8), "r"(1u) : "memory");
        asm volatile("mbarrier.init.shared.b64 [%0], %1;" :: "r"(sb + 16), "r"(1u) : "memory");
    }
    if (tid < 128) {
        ((float*)(smem + U_BIAS))[tid] = bias[tid];
        if (mode >= 2) {
            ((float*)(smem + U_LNS))[tid] = lns[tid];
            ((float*)(smem + U_LNB))[tid] = lnb[tid];
        }
    }
    {
        const uint4* sh = g_wimg_hi + (size_t)tileB * 2048;
        const uint4* sl = g_wimg_lo + (size_t)tileB * 2048;
        uint4* dh = (uint4*)(smem + PT_B);
        uint4* dl = (uint4*)(smem + PT_B + 32768);
        #pragma unroll
        for (int u = 0; u < 4; u++) { dh[tid + u*512] = sh[tid + u*512]; dl[tid + u*512] = sl[tid + u*512]; }
    }
    __syncthreads();
    uint32_t tmem;
    asm volatile("ld.shared.b32 %0, [%1];" : "=r"(tmem) : "r"(sb));
    const uint64_t bh = mk_desc(sb + PT_B), bl = mk_desc(sb + PT_B + 32768);
    const float* bias_s = (const float*)(smem + U_BIAS);

    int cnt = 0, prev_it = -1;
    float4 f[8];
    int it = blockIdx.x;
    if (it < ntiles) {
        const float* Ab = A + (size_t)it * 128 * 128;
        #pragma unroll
        for (int u = 0; u < 4; u++) {
            int g = tid + u * 512;
            int r = g >> 4, kg = (g & 15) << 3;
            f[2*u]   = *(const float4*)(Ab + (size_t)r * 128 + kg);
            f[2*u+1] = *(const float4*)(Ab + (size_t)r * 128 + kg + 4);
        }
    }
    for (; it < ntiles; it += gridDim.x, cnt++) {
        const int b = cnt & 1;
        char* abuf = smem + (b ? PT_A1 : PT_A0);
        #pragma unroll
        for (int u = 0; u < 4; u++) {
            int g = tid + u * 512;
            int r = g >> 4, kg = (g & 15) << 3;
            float v8[8];
            v8[0]=f[2*u].x; v8[1]=f[2*u].y; v8[2]=f[2*u].z; v8[3]=f[2*u].w;
            v8[4]=f[2*u+1].x; v8[5]=f[2*u+1].y; v8[6]=f[2*u+1].z; v8[7]=f[2*u+1].w;
            if (padA) {
                int grow = it * 128 + r;
                if ((grow & 63) >= lengths[grow >> 6]) {
                    #pragma unroll
                    for (int d = 0; d < 8; d++) v8[d] = -1.f;
                }
            }
            uint4 Hv, Lv; split8(v8, Hv, Lv);
            uint32_t o = tile_off(r, kg);
            *(uint4*)(abuf + o) = Hv;
            *(uint4*)(abuf + 32768 + o) = Lv;
        }
        __syncthreads();
        if (wid == 0 && elect1()) {
            asm volatile("fence.proxy.async.shared::cta;" ::: "memory");
            asm volatile("tcgen05.fence::after_thread_sync;" ::: "memory");
            uint64_t ah = mk_desc(sb + (b ? PT_A1 : PT_A0));
            uint64_t al = mk_desc(sb + (b ? PT_A1 : PT_A0) + 32768);
            uint32_t d = tmem + b * 128;
            #pragma unroll
            for (int s = 0; s < 8; s++) {
                uint64_t doff = (uint64_t)(((s >> 2) << 10) + ((s & 3) << 1));
                mma_ss(d, ah + doff, bh + doff, s > 0 ? 1u : 0u);
                mma_ss(d, ah + doff, bl + doff, 1u);
                mma_ss(d, al + doff, bh + doff, 1u);
            }
            asm volatile("tcgen05.commit.cta_group::1.mbarrier::arrive::one.shared::cluster.b64 [%0];"
                         :: "r"(sb + 8 + b * 8) : "memory");
        }
        {
            int nit = it + gridDim.x;
            if (nit < ntiles) {
                const float* Ab2 = A + (size_t)nit * 128 * 128;
                #pragma unroll
                for (int u = 0; u < 4; u++) {
                    int g = tid + u * 512;
                    int r = g >> 4, kg = (g & 15) << 3;
                    f[2*u]   = *(const float4*)(Ab2 + (size_t)r * 128 + kg);
                    f[2*u+1] = *(const float4*)(Ab2 + (size_t)r * 128 + kg + 4);
                }
            }
        }
        if (cnt > 0) {
            int pc = cnt - 1, pb = pc & 1;
            MBAR_WAIT(sb + 8 + pb * 8, (pc >> 1) & 1);
            asm volatile("tcgen05.fence::after_thread_sync;" ::: "memory");
            float v[32]; uint32_t vr[32];
            LDTM_X32(vr, tmem + pb * 128 + nh * 32);
            asm volatile("tcgen05.wait::ld.sync.aligned;" ::: "memory");
            #pragma unroll
            for (int j = 0; j < 32; j++) v[j] = __uint_as_float(vr[j]);
            asm volatile("tcgen05.fence::before_thread_sync;" ::: "memory");
            epi_tile(v, smem, smem + (pb ? PT_A1 : PT_A0), mode, prev_it * 128, nh, rl, wid, lid,
                     bias_s, res, pos, C, ldC, n0);
        }
        prev_it = it;
    }
    if (cnt > 0) {
        int pc = cnt - 1, pb = pc & 1;
        MBAR_WAIT(sb + 8 + pb * 8, (pc >> 1) & 1);
        asm volatile("tcgen05.fence::after_thread_sync;" ::: "memory");
        float v[32]; uint32_t vr[32];
        LDTM_X32(vr, tmem + pb * 128 + nh * 32);
        asm volatile("tcgen05.wait::ld.sync.aligned;" ::: "memory");
        #pragma unroll
        for (int j = 0; j < 32; j++) v[j] = __uint_as_float(vr[j]);
        asm volatile("tcgen05.fence::before_thread_sync;" ::: "memory");
        epi_tile(v, smem, smem + (pb ? PT_A0 : PT_A1), mode, prev_it * 128, nh, rl, wid, lid,
                 bias_s, res, pos, C, ldC, n0);
    }
    __syncthreads();
    if (tid == 0) {
        asm volatile("mbarrier.inval.shared.b64 [%0];" :: "r"(sb + 8) : "memory");
        asm volatile("mbarrier.inval.shared.b64 [%0];" :: "r"(sb + 16) : "memory");
    }
    __syncthreads();
    if (wid == 0) {
        asm volatile("tcgen05.relinquish_alloc_permit.cta_group::1.sync.aligned;");
        asm volatile("tcgen05.dealloc.cta_group::1.sync.aligned.b32 %0, %1;" :: "r"(tmem), "r"(256u));
    }
#endif
}

// ============== persistent K=128 NT=2 fused GEMM (single A buffer) ===========
// mode: 0 = bias, 1 = bias+relu. C row = [tile0 | tile1], ldC = 256.
// R14 change: fp32->bf16 hi/lo conversion hoisted BEFORE the A-buffer wait.
__global__ __launch_bounds__(512, 1) void tc_pgemm2(
    const float* __restrict__ A, float* __restrict__ C,
    const float* __restrict__ b0p, const float* __restrict__ b1p,
    int ntiles, int mode, int tileB)
{
#if TC_OK
    extern __shared__ char smem_raw[];
    uint32_t sb0 = smem_u32(smem_raw);
    uint32_t sb = (sb0 + 1023) & ~1023u;
    char* smem = smem_raw + (sb - sb0);
    const int tid = threadIdx.x;
    const int wid = tid >> 5, lid = tid & 31;
    const int nh = wid >> 2;
    const int rl = ((wid & 3) << 5) + lid;

    if (wid == 0)
        asm volatile("tcgen05.alloc.cta_group::1.sync.aligned.shared::cta.b32 [%0], %1;"
                     :: "r"(sb), "r"(512u) : "memory");
    if (tid == 0) {
        asm volatile("mbarrier.init.shared.b64 [%0], %1;" :: "r"(sb + 8), "r"(1u) : "memory");
        asm volatile("mbarrier.init.shared.b64 [%0], %1;" :: "r"(sb + 16), "r"(1u) : "memory");
    }
    if (tid < 128) ((float*)(smem + U_BIAS))[tid] = b0p[tid];
    else if (tid < 256) ((float*)(smem + U_BIAS))[tid] = b1p[tid - 128];
    for (int nt = 0; nt < 2; nt++) {
        const uint4* sh = g_wimg_hi + (size_t)(tileB + nt) * 2048;
        const uint4* sl = g_wimg_lo + (size_t)(tileB + nt) * 2048;
        uint4* dh = (uint4*)(smem + P2_B + nt * 65536);
        uint4* dl = (uint4*)(smem + P2_B + nt * 65536 + 32768);
        #pragma unroll
        for (int u = 0; u < 4; u++) { dh[tid + u*512] = sh[tid + u*512]; dl[tid + u*512] = sl[tid + u*512]; }
    }
    __syncthreads();
    uint32_t tmem;
    asm volatile("ld.shared.b32 %0, [%1];" : "=r"(tmem) : "r"(sb));
    const float* bias_s = (const float*)(smem + U_BIAS);
    char* scr16 = smem + P2_SCR;

    int cnt = 0, prev_it = -1;
    float4 f[8];
    int it = blockIdx.x;
    if (it < ntiles) {
        const float* Ab = A + (size_t)it * 128 * 128;
        #pragma unroll
        for (int u = 0; u < 4; u++) {
            int g = tid + u * 512;
            int r = g >> 4, kg = (g & 15) << 3;
            f[2*u]   = *(const float4*)(Ab + (size_t)r * 128 + kg);
            f[2*u+1] = *(const float4*)(Ab + (size_t)r * 128 + kg + 4);
        }
    }
    for (; it < ntiles; it += gridDim.x, cnt++) {
        const int b = cnt & 1;
        // pre-convert prefetched A(it) into registers (independent of A buffer)
        uint4 Hr[4], Lr[4];
        #pragma unroll
        for (int u = 0; u < 4; u++) {
            float v8[8];
            v8[0]=f[2*u].x; v8[1]=f[2*u].y; v8[2]=f[2*u].z; v8[3]=f[2*u].w;
            v8[4]=f[2*u+1].x; v8[5]=f[2*u+1].y; v8[6]=f[2*u+1].z; v8[7]=f[2*u+1].w;
            split8(v8, Hr[u], Lr[u]);
        }
        // wait for MMA(n-1) to release the single A buffer, then STS only
        if (cnt > 0) {
            int pc = cnt - 1;
            MBAR_WAIT(sb + 8 + (pc & 1) * 8, (pc >> 1) & 1);
        }
        #pragma unroll
        for (int u = 0; u < 4; u++) {
            int g = tid + u * 512;
            int r = g >> 4, kg = (g & 15) << 3;
            uint32_t o = tile_off(r, kg);
            *(uint4*)(smem + P2_A + o) = Hr[u];
            *(uint4*)(smem + P2_A + 32768 + o) = Lr[u];
        }
        __syncthreads();
        if (wid == 0 && elect1()) {
            asm volatile("fence.proxy.async.shared::cta;" ::: "memory");
            asm volatile("tcgen05.fence::after_thread_sync;" ::: "memory");
            uint64_t ah = mk_desc(sb + P2_A), al = mk_desc(sb + P2_A + 32768);
            #pragma unroll
            for (int nt = 0; nt < 2; nt++) {
                uint64_t bhd = mk_desc(sb + P2_B + nt * 65536);
                uint64_t bld = mk_desc(sb + P2_B + nt * 65536 + 32768);
                uint32_t d = tmem + b * 256 + nt * 128;
                #pragma unroll
                for (int s = 0; s < 8; s++) {
                    uint64_t doff = (uint64_t)(((s >> 2) << 10) + ((s & 3) << 1));
                    mma_ss(d, ah + doff, bhd + doff, s > 0 ? 1u : 0u);
                    mma_ss(d, ah + doff, bld + doff, 1u);
                    mma_ss(d, al + doff, bhd + doff, 1u);
                }
            }
            asm volatile("tcgen05.commit.cta_group::1.mbarrier::arrive::one.shared::cluster.b64 [%0];"
                         :: "r"(sb + 8 + b * 8) : "memory");
        }
        // prefetch next A (latency hidden under epilogue)
        {
            int nit = it + gridDim.x;
            if (nit < ntiles) {
                const float* Ab2 = A + (size_t)nit * 128 * 128;
                #pragma unroll
                for (int u = 0; u < 4; u++) {
                    int g = tid + u * 512;
                    int r = g >> 4, kg = (g & 15) << 3;
                    f[2*u]   = *(const float4*)(Ab2 + (size_t)r * 128 + kg);
                    f[2*u+1] = *(const float4*)(Ab2 + (size_t)r * 128 + kg + 4);
                }
            }
        }
        // epilogue of previous tile
        if (cnt > 0) {
            int pb = (cnt - 1) & 1;
            asm volatile("tcgen05.fence::after_thread_sync;" ::: "memory");
            #pragma unroll
            for (int nt = 0; nt < 2; nt++) {
                float v[32]; uint32_t vr[32];
                LDTM_X32(vr, tmem + pb * 256 + nt * 128 + nh * 32);
                asm volatile("tcgen05.wait::ld.sync.aligned;" ::: "memory");
                #pragma unroll
                for (int j = 0; j < 32; j++) v[j] = __uint_as_float(vr[j]);
                asm volatile("tcgen05.fence::before_thread_sync;" ::: "memory");
                epi_tile_lite(v, scr16, mode, prev_it * 128, nh, rl, tid,
                              bias_s + nt * 128, C, 256, nt * 128);
            }
        }
        prev_it = it;
    }
    if (cnt > 0) {
        int pc = cnt - 1, pb = pc & 1;
        MBAR_WAIT(sb + 8 + pb * 8, (pc >> 1) & 1);
        asm volatile("tcgen05.fence::after_thread_sync;" ::: "memory");
        #pragma unroll
        for (int nt = 0; nt < 2; nt++) {
            float v[32]; uint32_t vr[32];
            LDTM_X32(vr, tmem + pb * 256 + nt * 128 + nh * 32);
            asm volatile("tcgen05.wait::ld.sync.aligned;" ::: "memory");
            #pragma unroll
            for (int j = 0; j < 32; j++) v[j] = __uint_as_float(vr[j]);
            asm volatile("tcgen05.fence::before_thread_sync;" ::: "memory");
            epi_tile_lite(v, scr16, mode, prev_it * 128, nh, rl, tid,
                          bias_s + nt * 128, C, 256, nt * 128);
        }
    }
    __syncthreads();
    if (tid == 0) {
        asm volatile("mbarrier.inval.shared.b64 [%0];" :: "r"(sb + 8) : "memory");
        asm volatile("mbarrier.inval.shared.b64 [%0];" :: "r"(sb + 16) : "memory");
    }
    __syncthreads();
    if (wid == 0) {
        asm volatile("tcgen05.relinquish_alloc_permit.cta_group::1.sync.aligned;");
        asm volatile("tcgen05.dealloc.cta_group::1.sync.aligned.b32 %0, %1;" :: "r"(tmem), "r"(512u));
    }
#endif
}

// ======== generic GEMM: 2D grid, blockIdx.y = N-tile; one B tile per CTA ======
__global__ __launch_bounds__(512, 1) void tc_gemm(
    const float* __restrict__ A, float* __restrict__ C,
    const float* __restrict__ bias0, const float* __restrict__ bias1,
    const float* __restrict__ bias2,
    const float* __restrict__ res, const float* __restrict__ lns,
    const float* __restrict__ lnb,
    int KC, int NT, int mode, int tile0)
{
#if TC_OK
    extern __shared__ char smem_raw[];
    uint32_t sb0 = smem_u32(smem_raw);
    uint32_t sb = (sb0 + 1023) & ~1023u;
    char* smem = smem_raw + (sb - sb0);
    const int tid = threadIdx.x;
    const int wid = tid >> 5, lid = tid & 31;
    const int m0 = blockIdx.x * 128;
    const int nt = blockIdx.y;
    const int Ktot = KC * 128;
    const int N = NT * 128;
    const int nh = wid >> 2;
    const int rl = ((wid & 3) << 5) + lid;

    if (wid == 0)
        asm volatile("tcgen05.alloc.cta_group::1.sync.aligned.shared::cta.b32 [%0], %1;"
                     :: "r"(sb), "r"(128u) : "memory");
    if (tid == 0)
        asm volatile("mbarrier.init.shared.b64 [%0], %1;" :: "r"(sb + 8), "r"(1u) : "memory");
    {
        const float* bN = (nt == 0) ? bias0 : ((nt == 1) ? bias1 : bias2);
        if (tid < 128) {
            ((float*)(smem + U_BIAS))[tid] = bN[tid];
            if (mode >= 2) {
                ((float*)(smem + U_LNS))[tid] = lns[tid];
                ((float*)(smem + U_LNB))[tid] = lnb[tid];
            }
        }
    }
    __syncthreads();
    uint32_t tmem;
    asm volatile("ld.shared.b32 %0, [%1];" : "=r"(tmem) : "r"(sb));

    for (int kc = 0; kc < KC; kc++) {
        if (kc > 0) MBAR_WAIT(sb + 8, (kc - 1) & 1);
        const float* Ab = A + (size_t)m0 * Ktot + kc * 128;
        float4 f[8];
        #pragma unroll
        for (int u = 0; u < 4; u++) {
            int g = tid + u * 512;
            int r = g >> 4, kg = (g & 15) << 3;
            f[2*u]   = *(const float4*)(Ab + (size_t)r * Ktot + kg);
            f[2*u+1] = *(const float4*)(Ab + (size_t)r * Ktot + kg + 4);
        }
        #pragma unroll
        for (int u = 0; u < 4; u++) {
            int g = tid + u * 512;
            int r = g >> 4, kg = (g & 15) << 3;
            float v8[8];
            v8[0]=f[2*u].x; v8[1]=f[2*u].y; v8[2]=f[2*u].z; v8[3]=f[2*u].w;
            v8[4]=f[2*u+1].x; v8[5]=f[2*u+1].y; v8[6]=f[2*u+1].z; v8[7]=f[2*u+1].w;
            uint4 Hv, Lv; split8(v8, Hv, Lv);
            uint32_t o = tile_off(r, kg);
            *(uint4*)(smem + SM_AHI + o) = Hv;
            *(uint4*)(smem + SM_ALO + o) = Lv;
        }
        {
            int tI = tile0 + kc * NT + nt;
            const uint4* sh = g_wimg_hi + (size_t)tI * 2048;
            const uint4* sl = g_wimg_lo + (size_t)tI * 2048;
            uint4* dh = (uint4*)(smem + SM_B);
            uint4* dl = (uint4*)(smem + SM_B + 32768);
            #pragma unroll
            for (int u = 0; u < 4; u++) { dh[tid + u*512] = sh[tid + u*512]; dl[tid + u*512] = sl[tid + u*512]; }
        }
        __syncthreads();
        if (wid == 0 && elect1()) {
            asm volatile("fence.proxy.async.shared::cta;" ::: "memory");
            uint64_t ah = mk_desc(sb + SM_AHI), al = mk_desc(sb + SM_ALO);
            uint64_t bhd = mk_desc(sb + SM_B), bld = mk_desc(sb + SM_B + 32768);
            #pragma unroll
            for (int s = 0; s < 8; s++) {
                uint64_t doff = (uint64_t)(((s >> 2) << 10) + ((s & 3) << 1));
                uint32_t first = (kc == 0 && s == 0) ? 0u : 1u;
                mma_ss(tmem, ah + doff, bhd + doff, first);
                mma_ss(tmem, ah + doff, bld + doff, 1u);
                mma_ss(tmem, al + doff, bhd + doff, 1u);
            }
            asm volatile("tcgen05.commit.cta_group::1.mbarrier::arrive::one.shared::cluster.b64 [%0];"
                         :: "r"(sb + 8) : "memory");
        }
    }
    MBAR_WAIT(sb + 8, (KC - 1) & 1);
    asm volatile("tcgen05.fence::after_thread_sync;" ::: "memory");
    {
        float v[32]; uint32_t vr[32];
        LDTM_X32(vr, tmem + nh * 32);
        asm volatile("tcgen05.wait::ld.sync.aligned;" ::: "memory");
        #pragma unroll
        for (int j = 0; j < 32; j++) v[j] = __uint_as_float(vr[j]);
        asm volatile("tcgen05.fence::before_thread_sync;" ::: "memory");
        epi_tile(v, smem, smem + SM_AHI, mode, m0, nh, rl, wid, lid,
                 (const float*)(smem + U_BIAS), res, nullptr, C, N, nt * 128);
    }
    __syncthreads();
    if (tid == 0)
        asm volatile("mbarrier.inval.shared.b64 [%0];" :: "r"(sb + 8) : "memory");
    __syncthreads();
    if (wid == 0) {
        asm volatile("tcgen05.relinquish_alloc_permit.cta_group::1.sync.aligned;");
        asm volatile("tcgen05.dealloc.cta_group::1.sync.aligned.b32 %0, %1;" :: "r"(tmem), "r"(128u));
    }
#endif
}

// --------- temporal attention: one block per sequence, 8 heads x 64 lanes ----
#define ROWF 33
__global__ __launch_bounds__(512) void attn_seq_kernel(
    const float* __restrict__ Q, const float* __restrict__ Km,
    const float* __restrict__ Vm, float* __restrict__ O,
    const int* __restrict__ lengths, int ldkv)
{
    extern __shared__ float4 smf[];
    float4* ks4 = smf;
    float4* vs4 = smf + 64 * ROWF;
    float4* qm4 = smf + 2 * 64 * ROWF;
    const int n = blockIdx.x, tid = threadIdx.x;
    const int head = tid >> 6, i = tid & 63;
    const int ldkv4 = ldkv >> 2;
    const float4* Kb = (const float4*)(Km + (size_t)n * T_ * ldkv);
    const float4* Vb = (const float4*)(Vm + (size_t)n * T_ * ldkv);
    const float4* Qb = (const float4*)(Q  + (size_t)n * T_ * H_);
    #pragma unroll
    for (int u = 0; u < 4; u++) {
        int idx = tid + u * 512;
        int r = idx >> 5, c = idx & 31;
        ks4[r * ROWF + c] = Kb[r * ldkv4 + c];
        vs4[r * ROWF + c] = Vb[r * ldkv4 + c];
        qm4[r * ROWF + c] = Qb[r * 32 + c];
    }
    const int len = lengths[n];
    const int myv = (i < len);
    __syncthreads();
    const int c0 = head * 4;
    float4 q0 = qm4[i * ROWF + c0],     q1 = qm4[i * ROWF + c0 + 1],
           q2 = qm4[i * ROWF + c0 + 2], q3 = qm4[i * ROWF + c0 + 3];
    float m = -1e30f, s = 0.f, acc[16];
    #pragma unroll
    for (int d = 0; d < 16; d++) acc[d] = 0.f;
    for (int j = 0; j < len; j++) {
        float sc;
        if (myv) {
            float4 a0 = ks4[j*ROWF+c0], a1 = ks4[j*ROWF+c0+1],
                   a2 = ks4[j*ROWF+c0+2], a3 = ks4[j*ROWF+c0+3];
            float d = a0.x*q0.x + a0.y*q0.y + a0.z*q0.z + a0.w*q0.w
                    + a1.x*q1.x + a1.y*q1.y + a1.z*q1.z + a1.w*q1.w
                    + a2.x*q2.x + a2.y*q2.y + a2.z*q2.z + a2.w*q2.w
                    + a3.x*q3.x + a3.y*q3.y + a3.z*q3.z + a3.w*q3.w;
            sc = d * SCALE_;
        } else sc = -1e9f;
        float w;
        if (sc > m) {
            float c = __expf(m - sc);
            s = s * c + 1.f;
            #pragma unroll
            for (int d = 0; d < 16; d++) acc[d] *= c;
            m = sc; w = 1.f;
        } else { w = __expf(sc - m); s += w; }
        float4 b0 = vs4[j*ROWF+c0], b1 = vs4[j*ROWF+c0+1],
               b2 = vs4[j*ROWF+c0+2], b3 = vs4[j*ROWF+c0+3];
        acc[0]  += w*b0.x; acc[1]  += w*b0.y; acc[2]  += w*b0.z; acc[3]  += w*b0.w;
        acc[4]  += w*b1.x; acc[5]  += w*b1.y; acc[6]  += w*b1.z; acc[7]  += w*b1.w;
        acc[8]  += w*b2.x; acc[9]  += w*b2.y; acc[10] += w*b2.z; acc[11] += w*b2.w;
        acc[12] += w*b3.x; acc[13] += w*b3.y; acc[14] += w*b3.z; acc[15] += w*b3.w;
    }
    if (!myv) {
        for (int j = len; j < T_; j++) {
            s += 1.f;
            float4 b0 = vs4[j*ROWF+c0], b1 = vs4[j*ROWF+c0+1],
                   b2 = vs4[j*ROWF+c0+2], b3 = vs4[j*ROWF+c0+3];
            acc[0]  += b0.x; acc[1]  += b0.y; acc[2]  += b0.z; acc[3]  += b0.w;
            acc[4]  += b1.x; acc[5]  += b1.y; acc[6]  += b1.z; acc[7]  += b1.w;
            acc[8]  += b2.x; acc[9]  += b2.y; acc[10] += b2.z; acc[11] += b2.w;
            acc[12] += b3.x; acc[13] += b3.y; acc[14] += b3.z; acc[15] += b3.w;
        }
    }
    float inv = 1.f / s;
    __syncthreads();
    qm4[i*ROWF+c0]   = make_float4(acc[0]*inv,  acc[1]*inv,  acc[2]*inv,  acc[3]*inv);
    qm4[i*ROWF+c0+1] = make_float4(acc[4]*inv,  acc[5]*inv,  acc[6]*inv,  acc[7]*inv);
    qm4[i*ROWF+c0+2] = make_float4(acc[8]*inv,  acc[9]*inv,  acc[10]*inv, acc[11]*inv);
    qm4[i*ROWF+c0+3] = make_float4(acc[12]*inv, acc[13]*inv, acc[14]*inv, acc[15]*inv);
    __syncthreads();
    float4* Ob = (float4*)(O + (size_t)n * T_ * H_);
    #pragma unroll
    for (int u = 0; u < 4; u++) {
        int idx = tid + u * 512;
        int r = idx >> 5, c = idx & 31;
        Ob[idx] = qm4[r * ROWF + c];
    }
}

// ---------------- spatial attention ----------------
template <int L, bool SPATIAL>
__global__ __launch_bounds__(L) void attn_kernel(
    const float* __restrict__ Q, const float* __restrict__ Km,
    const float* __restrict__ Vm, float* __restrict__ O,
    const int* __restrict__ lengths, int ld)
{
    const int head = blockIdx.x, n = blockIdx.y, i = threadIdx.x;
    __shared__ float ks[L][DHP], vs[L][DHP], qs[L][DHP];
    __shared__ int vm[L];
    const size_t rowbase = (size_t)n * L;
    const int coff = head * DH_;
    #pragma unroll
    for (int x = 0; x < 4; x++) {
        int idx = x * L + i;
        int j = idx >> 2, q = (idx & 3) * 4;
        *(float4*)&ks[j][q] = *(const float4*)(Km + (rowbase + j) * ld + coff + q);
        *(float4*)&vs[j][q] = *(const float4*)(Vm + (rowbase + j) * ld + coff + q);
        *(float4*)&qs[j][q] = *(const float4*)(Q  + (rowbase + j) * ld + coff + q);
    }
    int len = 0, myv;
    if (SPATIAL) { myv = (lengths[n * S_ + i] > 0) ? 1 : 0; vm[i] = myv; }
    else         { len = lengths[n]; myv = (i < len) ? 1 : 0; }
    __syncthreads();
    float qr[DH_];
    #pragma unroll
    for (int d = 0; d < DH_; d++) qr[d] = qs[i][d];

    float m = -1e30f, s = 0.f, acc[DH_];
    #pragma unroll
    for (int dd = 0; dd < DH_; dd++) acc[dd] = 0.f;

    const int jmax = SPATIAL ? L : len;
    for (int j = 0; j < jmax; j++) {
        if (SPATIAL && !vm[j]) continue;
        float sc;
        if (myv) {
            const float4* kp = (const float4*)&ks[j][0];
            float4 a0 = kp[0], a1 = kp[1], a2 = kp[2], a3 = kp[3];
            float d = a0.x*qr[0] + a0.y*qr[1] + a0.z*qr[2] + a0.w*qr[3]
                    + a1.x*qr[4] + a1.y*qr[5] + a1.z*qr[6] + a1.w*qr[7]
                    + a2.x*qr[8] + a2.y*qr[9] + a2.z*qr[10] + a2.w*qr[11]
                    + a3.x*qr[12] + a3.y*qr[13] + a3.z*qr[14] + a3.w*qr[15];
            sc = d * SCALE_;
        } else sc = -1e9f;
        float w;
        if (sc > m) {
            float c = __expf(m - sc);
            s = s * c + 1.f;
            #pragma unroll
            for (int dd = 0; dd < DH_; dd++) acc[dd] *= c;
            m = sc; w = 1.f;
        } else {
            w = __expf(sc - m);
            s += w;
        }
        const float4* vp = (const float4*)&vs[j][0];
        float4 b0 = vp[0], b1 = vp[1], b2 = vp[2], b3 = vp[3];
        acc[0]  += w*b0.x; acc[1]  += w*b0.y; acc[2]  += w*b0.z; acc[3]  += w*b0.w;
        acc[4]  += w*b1.x; acc[5]  += w*b1.y; acc[6]  += w*b1.z; acc[7]  += w*b1.w;
        acc[8]  += w*b2.x; acc[9]  += w*b2.y; acc[10] += w*b2.z; acc[11] += w*b2.w;
        acc[12] += w*b3.x; acc[13] += w*b3.y; acc[14] += w*b3.z; acc[15] += w*b3.w;
    }
    if (!myv) {
        for (int j = 0; j < L; j++) {
            bool inv_key = SPATIAL ? (!vm[j]) : (j >= len);
            if (!inv_key) continue;
            s += 1.f;
            const float4* vp = (const float4*)&vs[j][0];
            float4 b0 = vp[0], b1 = vp[1], b2 = vp[2], b3 = vp[3];
            acc[0]  += b0.x; acc[1]  += b0.y; acc[2]  += b0.z; acc[3]  += b0.w;
            acc[4]  += b1.x; acc[5]  += b1.y; acc[6]  += b1.z; acc[7]  += b1.w;
            acc[8]  += b2.x; acc[9]  += b2.y; acc[10] += b2.z; acc[11] += b2.w;
            acc[12] += b3.x; acc[13] += b3.y; acc[14] += b3.z; acc[15] += b3.w;
        }
    }
    float inv = 1.f / s;
    __syncthreads();
    #pragma unroll
    for (int dd = 0; dd < DH_; dd++) qs[i][dd] = acc[dd] * inv;
    __syncthreads();
    #pragma unroll
    for (int x = 0; x < 4; x++) {
        int idx = x * L + i;
        int j = idx >> 2, q = (idx & 3) * 4;
        *(float4*)(O + (rowbase + j) * H_ + coff + q) = *(const float4*)&qs[j][q];
    }
}

__global__ __launch_bounds__(T_) void attn_t0_kernel(
    const float* __restrict__ Qs, const float* __restrict__ Km,
    const float* __restrict__ Vm, float* __restrict__ O,
    const int* __restrict__ lengths, int ldkv)
{
    const int head = blockIdx.x, n = blockIdx.y, j = threadIdx.x;
    __shared__ float sw[T_];
    const int len = lengths[n], coff = head * DH_;
    const float* qp = Qs + (size_t)n * H_ + coff;
    const float* kp = Km + ((size_t)n * T_ + j) * ldkv + coff;
    float d = 0.f;
    #pragma unroll
    for (int dd = 0; dd < DH_; dd++) d += qp[dd] * kp[dd];
    float sc = (j < len) ? d * SCALE_ : -1e9f;
    sw[j] = sc;
    __syncthreads();
    float m = -1e30f;
    #pragma unroll 8
    for (int jj = 0; jj < T_; jj++) m = fmaxf(m, sw[jj]);
    float w = __expf(sc - m);
    __syncthreads();
    sw[j] = w;
    __syncthreads();
    if (j < DH_) {
        float s = 0.f, acc = 0.f;
        for (int jj = 0; jj < T_; jj++) {
            float wj = sw[jj];
            s += wj;
            acc += wj * Vm[((size_t)n * T_ + jj) * ldkv + coff + j];
        }
        O[(size_t)n * H_ + coff + j] = acc / s;
    }
}

__global__ void gather_t0_kernel(const float* __restrict__ X, float* __restrict__ Xg)
{
    int idx = blockIdx.x * blockDim.x + threadIdx.x;
    if (idx >= MS_ * H_) return;
    Xg[idx] = X[((size_t)(idx / H_) * T_) * H_ + (idx % H_)];
}
__global__ void final_kernel(const float* __restrict__ Xs, float* __restrict__ out)
{
    int idx = blockIdx.x * blockDim.x + threadIdx.x;
    if (idx >= B_ * T_ * H_) return;
    int h = idx % H_, t = (idx / H_) % T_, b = idx / (T_ * H_);
    out[idx] = Xs[((size_t)b * S_ + t) * H_ + h];
}

// ---------------- host ----------------
#define PGRID_ 152
#define ATTN_SMEM (3 * 64 * ROWF * 16)
static void tcP(const float* A, float* C, const float* bias, const float* res,
                const float* lns, const float* lnb, const float* pos, const int* len,
                int ntiles, int mode, int tileB, int padA, int ldC, int n0)
{
    tc_pgemm<<<PGRID_, 512, PT_SMEM + 1024>>>(A, C, bias, res, lns, lnb, pos, len,
                                              ntiles, mode, tileB, padA, ldC, n0);
}
static void tcP2(const float* A, float* C, const float* b0p, const float* b1p,
                 int ntiles, int mode, int tileB)
{
    tc_pgemm2<<<PGRID_, 512, P2_SMEM + 1024>>>(A, C, b0p, b1p, ntiles, mode, tileB);
}
static void tcG(const float* A, float* C, const float* b0, const float* b1p,
                const float* b2p, const float* res, const float* lns, const float* lnb,
                int M, int KC, int NT, int mode, int tile0)
{
    dim3 g(M / 128, NT);
    tc_gemm<<<g, 512, SG_SMEM + 1024>>>(A, C, b0, b1p, b2p, res, lns, lnb,
                                        KC, NT, mode, tile0);
}

extern "C" void kernel_launch(void* const* d_in, const int* in_sizes, int n_in,
                              void* d_out, int out_size)
{
    const float* poly = (const float*)d_in[0];
    const int*   len  = (const int*)  d_in[1];
    const float* pw   = (const float*)d_in[2];
    const float* pb   = (const float*)d_in[3];
    const float* pls  = (const float*)d_in[4];
    const float* plb  = (const float*)d_in[5];
    const float* pos  = (const float*)d_in[6];
    const float* Wq   = (const float*)d_in[7];
    const float* bq   = (const float*)d_in[8];
    const float* Wk   = (const float*)d_in[9];
    const float* bk   = (const float*)d_in[10];
    const float* Wv   = (const float*)d_in[11];
    const float* bv   = (const float*)d_in[12];
    const float* Wo   = (const float*)d_in[13];
    const float* bo   = (const float*)d_in[14];
    const float* l1s  = (const float*)d_in[15];
    const float* l1b  = (const float*)d_in[16];
    const float* W1   = (const float*)d_in[17];
    const float* b1   = (const float*)d_in[18];
    const float* W2   = (const float*)d_in[19];
    const float* b2   = (const float*)d_in[20];
    const float* l2s  = (const float*)d_in[21];
    const float* l2b  = (const float*)d_in[22];
    float* out = (float*)d_out;

    cudaFuncSetAttribute(tc_gemm, cudaFuncAttributeMaxDynamicSharedMemorySize, SG_SMEM + 1024);
    cudaFuncSetAttribute(tc_pgemm, cudaFuncAttributeMaxDynamicSharedMemorySize, PT_SMEM + 1024);
    cudaFuncSetAttribute(tc_pgemm2, cudaFuncAttributeMaxDynamicSharedMemorySize, P2_SMEM + 1024);
    cudaFuncSetAttribute(attn_seq_kernel, cudaFuncAttributeMaxDynamicSharedMemorySize, ATTN_SMEM);

    float *x, *tmp, *q, *hb, *xs, *qs, *qkv, *ts, *hs;
    cudaGetSymbolAddress((void**)&x, g_x);   cudaGetSymbolAddress((void**)&tmp, g_tmp);
    cudaGetSymbolAddress((void**)&q, g_q);   cudaGetSymbolAddress((void**)&hb, g_h);
    cudaGetSymbolAddress((void**)&xs, g_xs); cudaGetSymbolAddress((void**)&qs, g_qs);
    cudaGetSymbolAddress((void**)&qkv, g_qkv);
    cudaGetSymbolAddress((void**)&ts, g_ts); cudaGetSymbolAddress((void**)&hs, g_hs);

    const int NTIL0 = M0_ / 128;  // 1024

    PrepArgs pa{pw, Wq, Wk, Wv, Wo, W1, W2};
    prep_kernel<<<NTILES_, 256>>>(pa);

    // embed: proj (pad fused into A staging) + LN + relu + pos
    tcP(poly, x, pb, nullptr, pls, plb, pos, len, NTIL0, 3, 0, 1, 128, 0);

    // block 0 (temporal, full); tiles 1..8
    tcP(x, q, bq, nullptr, nullptr, nullptr, nullptr, nullptr, NTIL0, 0, 1, 0, 128, 0);
    tcP2(x, hb, bk, bv, NTIL0, 0, 2);                      // K|V fused -> hb [M0,256]
    attn_seq_kernel<<<B_ * S_, 512, ATTN_SMEM>>>(q, hb, hb + 128, tmp, len, 256);
    tcP(tmp, x, bo, x, l1s, l1b, nullptr, nullptr, NTIL0, 2, 4, 0, 128, 0);
    tcP2(x, hb, b1, b1 + 128, NTIL0, 1, 5);                // FFN1 fused -> hb [M0,256]
    tcG(hb, x, b2, nullptr, nullptr, x, l2s, l2b, M0_, 2, 1, 2, 7);

    // block 1 (temporal; K/V full, rest t=0 only); tiles 9..16
    {
        const int t0 = 9;
        tcP2(x, hb, bk + H_, bv + H_, NTIL0, 0, t0 + 1);   // K|V fused -> hb
        gather_t0_kernel<<<(MS_ * H_ + 255) / 256, 256>>>(x, xs);
        tcG(xs, qs, bq + H_, nullptr, nullptr, nullptr, nullptr, nullptr, MS_, 1, 1, 0, t0);
        attn_t0_kernel<<<dim3(NH_, MS_), T_>>>(qs, hb, hb + 128, ts, len, 256);
        tcG(ts, xs, bo + H_, nullptr, nullptr, xs, l1s + H_, l1b + H_, MS_, 1, 1, 2, t0 + 3);
        tcG(xs, hs, b1 + FF_, b1 + FF_ + 128, nullptr, nullptr, nullptr, nullptr, MS_, 1, 2, 1, t0 + 4);
        tcG(hs, xs, b2 + H_, nullptr, nullptr, xs, l2s + H_, l2b + H_, MS_, 2, 1, 2, t0 + 6);
    }

    // blocks 2,3 (spatial compact)
    for (int i = 2; i < NL_; i++) {
        const int t0 = 1 + i * 8;
        tcG(xs, qkv, bq + i * H_, bk + i * H_, bv + i * H_, nullptr, nullptr, nullptr,
            MS_, 1, 3, 0, t0);
        attn_kernel<S_, true><<<dim3(NH_, B_), S_>>>(qkv, qkv + 128, qkv + 256, ts, len, 384);
        tcG(ts, xs, bo + i * H_, nullptr, nullptr, xs, l1s + i * H_, l1b + i * H_, MS_, 1, 1, 2, t0 + 3);
        tcG(xs, hs, b1 + i * FF_, b1 + i * FF_ + 128, nullptr, nullptr, nullptr, nullptr,
            MS_, 1, 2, 1, t0 + 4);
        tcG(hs, xs, b2 + i * H_, nullptr, nullptr, xs, l2s + i * H_, l2b + i * H_, MS_, 2, 1, 2, t0 + 6);
    }

    final_kernel<<<(B_ * T_ * H_ + 255) / 256, 256>>>(xs, out);
    (void)in_sizes; (void)n_in; (void)out_size;
}

// round 15
// speedup vs baseline: 1.2258x; 1.0625x over previous
#include <cuda_runtime.h>
#include <cuda_bf16.h>
#include <cstdint>

#define B_  16
#define S_  128
#define T_  64
#define H_  128
#define NH_ 8
#define DH_ 16
#define DHP 20
#define FF_ 256
#define M0_ (B_*S_*T_)
#define MS_ (B_*S_)
#define SCALE_ 0.25f

#if defined(__CUDA_ARCH__) && (defined(__CUDA_ARCH_FEAT_SM103_ALL) || \
    defined(__CUDA_ARCH_FEAT_SM100_ALL) || defined(__CUDA_ARCH_SPECIFIC__) || \
    defined(__CUDA_ARCH_FAMILY_SPECIFIC__))
#define TC_OK 1
#else
#define TC_OK 0
#endif

__device__ float g_x  [(size_t)M0_ * H_];
__device__ float g_tmp[(size_t)M0_ * H_];
__device__ float g_q  [(size_t)M0_ * H_];
__device__ float g_h  [(size_t)M0_ * FF_];
__device__ float g_xs [(size_t)MS_ * H_];
__device__ float g_qs [(size_t)MS_ * H_];
__device__ float g_qkv[(size_t)MS_ * 384];
__device__ float g_ts [(size_t)MS_ * H_];
#define NTILES_ 33
__device__ uint4 g_wimg_hi[(size_t)NTILES_ * 2048];
__device__ uint4 g_wimg_lo[(size_t)NTILES_ * 2048];

__device__ __forceinline__ uint32_t smem_u32(const void* p) {
    uint32_t a;
    asm("{ .reg .u64 t; cvta.to.shared.u64 t, %1; cvt.u32.u64 %0, t; }" : "=r"(a) : "l"(p));
    return a;
}
__device__ __forceinline__ uint32_t elect1() {
    uint32_t p;
    asm volatile("{\n\t.reg .pred p;\n\telect.sync _|p, 0xFFFFFFFF;\n\tselp.b32 %0, 1, 0, p;\n\t}" : "=r"(p));
    return p;
}
__device__ __forceinline__ uint32_t tile_off(int r, int c) {
    uint32_t off = (uint32_t)((((r >> 3) + ((c >> 6) << 4)) << 10) + ((r & 7) << 7) + ((c & 63) << 1));
    return off ^ ((off >> 3) & 0x70);
}
__device__ __forceinline__ uint32_t scr_off(int row, int g) {
    return (uint32_t)(row * 512 + (((g ^ row) & 7) << 4) + ((g & 24) << 4));
}
__device__ __forceinline__ void split8(const float* a0, uint4& Hv, uint4& Lv) {
    uint32_t h[4], l[4];
    #pragma unroll
    for (int p = 0; p < 4; p++) {
        float x = a0[2 * p], y = a0[2 * p + 1];
        __nv_bfloat162 hh = __floats2bfloat162_rn(x, y);
        __nv_bfloat162 ll = __floats2bfloat162_rn(x - __bfloat162float(hh.x), y - __bfloat162float(hh.y));
        h[p] = *reinterpret_cast<uint32_t*>(&hh);
        l[p] = *reinterpret_cast<uint32_t*>(&ll);
    }
    Hv = make_uint4(h[0], h[1], h[2], h[3]);
    Lv = make_uint4(l[0], l[1], l[2], l[3]);
}

#if TC_OK
#define MBAR_WAIT(mbar, ph) do { \
    uint32_t _m = (mbar), _p = (ph), _d; \
    asm volatile("{\n\t.reg .pred p;\n\tmbarrier.try_wait.parity.acquire.cta.shared::cta.b64 p, [%1], %2;\n\tselp.b32 %0, 1, 0, p;\n\t}" \
        : "=r"(_d) : "r"(_m), "r"(_p) : "memory"); \
    if (!_d) { \
        asm volatile("{\n\t.reg .pred P1;\n\tWL_%=:\n\tmbarrier.try_wait.parity.acquire.cta.shared::cta.b64 P1, [%0], %1, 0x989680;\n\t@P1 bra.uni WD_%=;\n\tbra.uni WL_%=;\n\tWD_%=:\n\t}" \
            :: "r"(_m), "r"(_p) : "memory"); \
    } \
} while(0)
#define LDTM_X32(r, addr) \
    asm volatile("tcgen05.ld.sync.aligned.32x32b.x32.b32 " \
        "{%0,%1,%2,%3,%4,%5,%6,%7,%8,%9,%10,%11,%12,%13,%14,%15," \
        "%16,%17,%18,%19,%20,%21,%22,%23,%24,%25,%26,%27,%28,%29,%30,%31}, [%32];" \
        : "=r"((r)[0]),"=r"((r)[1]),"=r"((r)[2]),"=r"((r)[3]),"=r"((r)[4]),"=r"((r)[5]),"=r"((r)[6]),"=r"((r)[7]), \
          "=r"((r)[8]),"=r"((r)[9]),"=r"((r)[10]),"=r"((r)[11]),"=r"((r)[12]),"=r"((r)[13]),"=r"((r)[14]),"=r"((r)[15]), \
          "=r"((r)[16]),"=r"((r)[17]),"=r"((r)[18]),"=r"((r)[19]),"=r"((r)[20]),"=r"((r)[21]),"=r"((r)[22]),"=r"((r)[23]), \
          "=r"((r)[24]),"=r"((r)[25]),"=r"((r)[26]),"=r"((r)[27]),"=r"((r)[28]),"=r"((r)[29]),"=r"((r)[30]),"=r"((r)[31]) \
        : "r"(addr))
#define DESC_BASE ((2ULL << 61) | (1ULL << 46) | (64ULL << 32) | (1ULL << 16))
__device__ __forceinline__ uint64_t mk_desc(uint32_t addr) {
    return DESC_BASE | ((uint64_t)(addr >> 4) & 0x3FFF);
}
#define IDESC_ 0x8200490u
__device__ __forceinline__ void mma_ss(uint32_t d, uint64_t a, uint64_t b, uint32_t en) {
    asm volatile(
        "{\n\t.reg .pred p;\n\tsetp.ne.u32 p, %5, 0;\n\t"
        "tcgen05.mma.cta_group::1.kind::f16 [%0], %1, %2, %3, {%4, %4, %4, %4}, p;\n\t}"
        :: "r"(d), "l"(a), "l"(b), "r"(IDESC_), "r"(0u), "r"(en) : "memory");
}
#endif

// ---------------- weight prep ----------------
struct PrepArgs { const float *proj, *Wq, *Wk, *Wv, *Wo, *W1, *W2; };
__global__ __launch_bounds__(256) void prep_kernel(PrepArgs a) {
    const int t = blockIdx.x, tid = threadIdx.x;
    const float* src; int ldn = 128, k0 = 0, n0 = 0;
    if (t == 0) { src = a.proj; }
    else {
        int i = (t - 1) >> 3, j = (t - 1) & 7;
        const int HH = H_ * H_, HF = H_ * FF_;
        switch (j) {
            case 0: src = a.Wq + i * HH; break;
            case 1: src = a.Wk + i * HH; break;
            case 2: src = a.Wv + i * HH; break;
            case 3: src = a.Wo + i * HH; break;
            case 4: src = a.W1 + i * HF; ldn = 256; break;
            case 5: src = a.W1 + i * HF; ldn = 256; n0 = 128; break;
            case 6: src = a.W2 + i * HF; break;
            default: src = a.W2 + i * HF; k0 = 128; break;
        }
    }
    char* dh = (char*)(g_wimg_hi + (size_t)t * 2048);
    char* dl = (char*)(g_wimg_lo + (size_t)t * 2048);
    for (int g = tid; g < 2048; g += 256) {
        int n = g >> 4, kg = (g & 15) << 3;
        float v[8];
        #pragma unroll
        for (int d = 0; d < 8; d++) v[d] = src[(size_t)(k0 + kg + d) * ldn + n0 + n];
        uint4 Hv, Lv; split8(v, Hv, Lv);
        uint32_t o = tile_off(n, kg);
        *(uint4*)(dh + o) = Hv; *(uint4*)(dl + o) = Lv;
    }
}

// ---------------- smem layouts ----------------
#define U_BIAS 64
#define U_B2   1088
#define U_LNS  1600
#define U_LNB  2112
#define U_PSUM 2624
#define U_PSQ  4672
#define PT_A0   8192
#define PT_A1   73728
#define PT_B    139264
#define PT_SMEM (PT_B + 65536)
#define SM_AHI  8192
#define SM_ALO  40960
#define SM_B    73728
#define SG_SMEM (SM_B + 65536)
#define P2_A    8192
#define P2_B    73728
#define P2_SCR  204800
#define P2_SMEM (P2_SCR + 16384)
#define PF_A    8192
#define PF_B0   73728
#define PF_B1   139264
#define PF_SCR  204800
#define PF_SMEM (PF_SCR + 16384)

#if TC_OK
// ---- full epilogue (64KB scratch) ----
__device__ __forceinline__ void epi_tile(
    float* v, char* smem, char* scr, int mode, int tile_row0,
    int nh, int rl, int wid, int lid,
    const float* bias_s, const float* res, const float* pos,
    float* C, int ldC, int ncolbase)
{
    const int bcol = nh * 32;
    #pragma unroll
    for (int j = 0; j < 32; j++) v[j] += bias_s[bcol + j];
    if (mode == 1) {
        #pragma unroll
        for (int j = 0; j < 32; j++) v[j] = fmaxf(v[j], 0.f);
    }
    if (mode == 2) {
        #pragma unroll
        for (int rr = 0; rr < 8; rr++) {
            int row = wid * 8 + rr;
            float4 x = *(const float4*)(res + (size_t)(tile_row0 + row) * 128 + lid * 4);
            *(float4*)(scr + scr_off(row, lid)) = x;
        }
        __syncthreads();
        #pragma unroll
        for (int j4 = 0; j4 < 8; j4++) {
            float4 r4 = *(const float4*)(scr + scr_off(rl, (bcol >> 2) + j4));
            v[4*j4+0] += r4.x; v[4*j4+1] += r4.y; v[4*j4+2] += r4.z; v[4*j4+3] += r4.w;
        }
    }
    if (mode >= 2) {
        float s = 0.f, qq = 0.f;
        #pragma unroll
        for (int j = 0; j < 32; j++) { s += v[j]; qq += v[j] * v[j]; }
        ((float*)(smem + U_PSUM))[nh * 128 + rl] = s;
        ((float*)(smem + U_PSQ ))[nh * 128 + rl] = qq;
        __syncthreads();
        float ts = 0.f, tq = 0.f;
        #pragma unroll
        for (int g = 0; g < 4; g++) {
            ts += ((float*)(smem + U_PSUM))[g * 128 + rl];
            tq += ((float*)(smem + U_PSQ ))[g * 128 + rl];
        }
        __syncthreads();
        float mean = ts * (1.f / 128.f);
        float rstd = rsqrtf(tq * (1.f / 128.f) - mean * mean + 1e-5f);
        const float* Ls = (const float*)(smem + U_LNS) + bcol;
        const float* Lb = (const float*)(smem + U_LNB) + bcol;
        #pragma unroll
        for (int j = 0; j < 32; j++) v[j] = (v[j] - mean) * rstd * Ls[j] + Lb[j];
        if (mode == 3) {
            #pragma unroll
            for (int rr = 0; rr < 8; rr++) {
                int row = wid * 8 + rr;
                float4 x = *(const float4*)(pos + (size_t)((tile_row0 + row) & 63) * 128 + lid * 4);
                *(float4*)(scr + scr_off(row, lid)) = x;
            }
            __syncthreads();
            #pragma unroll
            for (int j4 = 0; j4 < 8; j4++) {
                float4 p4 = *(const float4*)(scr + scr_off(rl, (bcol >> 2) + j4));
                v[4*j4+0] = fmaxf(v[4*j4+0], 0.f) + p4.x;
                v[4*j4+1] = fmaxf(v[4*j4+1], 0.f) + p4.y;
                v[4*j4+2] = fmaxf(v[4*j4+2], 0.f) + p4.z;
                v[4*j4+3] = fmaxf(v[4*j4+3], 0.f) + p4.w;
            }
            __syncthreads();
        }
    }
    #pragma unroll
    for (int j4 = 0; j4 < 8; j4++)
        *(float4*)(scr + scr_off(rl, (bcol >> 2) + j4)) =
            make_float4(v[4*j4], v[4*j4+1], v[4*j4+2], v[4*j4+3]);
    __syncthreads();
    #pragma unroll
    for (int rr = 0; rr < 8; rr++) {
        int row = wid * 8 + rr;
        float4 x = *(const float4*)(scr + scr_off(row, lid));
        *(float4*)(C + (size_t)(tile_row0 + row) * ldC + ncolbase + lid * 4) = x;
    }
    __syncthreads();
}

// ---- lite epilogue via 16KB scratch ----
__device__ __forceinline__ void epi_tile_lite(
    float* v, char* scr16, int mode, int tile_row0,
    int nh, int rl, int tid, const float* bias_s,
    float* C, int ldC, int ncolbase)
{
    const int bcol = nh * 32;
    #pragma unroll
    for (int j = 0; j < 32; j++) v[j] += bias_s[bcol + j];
    if (mode == 1) {
        #pragma unroll
        for (int j = 0; j < 32; j++) v[j] = fmaxf(v[j], 0.f);
    }
    #pragma unroll
    for (int p = 0; p < 4; p++) {
        if ((rl >> 5) == p) {
            int r32 = rl & 31;
            #pragma unroll
            for (int j4 = 0; j4 < 8; j4++)
                *(float4*)(scr16 + scr_off(r32, (bcol >> 2) + j4)) =
                    make_float4(v[4*j4], v[4*j4+1], v[4*j4+2], v[4*j4+3]);
        }
        __syncthreads();
        #pragma unroll
        for (int e = 0; e < 2; e++) {
            int id = tid + e * 512;
            int r32 = id >> 5, c = id & 31;
            float4 x = *(const float4*)(scr16 + scr_off(r32, c));
            *(float4*)(C + (size_t)(tile_row0 + p * 32 + r32) * ldC + ncolbase + c * 4) = x;
        }
        __syncthreads();
    }
}
#endif

// ======================= persistent K=128 NT=1 GEMM =======================
__global__ __launch_bounds__(512, 1) void tc_pgemm(
    const float* __restrict__ A, float* __restrict__ C,
    const float* __restrict__ bias, const float* __restrict__ res,
    const float* __restrict__ lns, const float* __restrict__ lnb,
    const float* __restrict__ pos, const int* __restrict__ lengths,
    int ntiles, int mode, int tileB, int padA, int ldC, int n0)
{
#if TC_OK
    extern __shared__ char smem_raw[];
    uint32_t sb0 = smem_u32(smem_raw);
    uint32_t sb = (sb0 + 1023) & ~1023u;
    char* smem = smem_raw + (sb - sb0);
    const int tid = threadIdx.x;
    const int wid = tid >> 5, lid = tid & 31;
    const int nh = wid >> 2;
    const int rl = ((wid & 3) << 5) + lid;

    if (wid == 0)
        asm volatile("tcgen05.alloc.cta_group::1.sync.aligned.shared::cta.b32 [%0], %1;"
                     :: "r"(sb), "r"(256u) : "memory");
    if (tid == 0) {
        asm volatile("mbarrier.init.shared.b64 [%0], %1;" :: "r"(sb + 8), "r"(1u) : "memory");
        asm volatile("mbarrier.init.shared.b64 [%0], %1;" :: "r"(sb + 16), "r"(1u) : "memory");
    }
    if (tid < 128) {
        ((float*)(smem + U_BIAS))[tid] = bias[tid];
        if (mode >= 2) {
            ((float*)(smem + U_LNS))[tid] = lns[tid];
            ((float*)(smem + U_LNB))[tid] = lnb[tid];
        }
    }
    {
        const uint4* sh = g_wimg_hi + (size_t)tileB * 2048;
        const uint4* sl = g_wimg_lo + (size_t)tileB * 2048;
        uint4* dh = (uint4*)(smem + PT_B);
        uint4* dl = (uint4*)(smem + PT_B + 32768);
        #pragma unroll
        for (int u = 0; u < 4; u++) { dh[tid + u*512] = sh[tid + u*512]; dl[tid + u*512] = sl[tid + u*512]; }
    }
    __syncthreads();
    uint32_t tmem;
    asm volatile("ld.shared.b32 %0, [%1];" : "=r"(tmem) : "r"(sb));
    const uint64_t bh = mk_desc(sb + PT_B), bl = mk_desc(sb + PT_B + 32768);
    const float* bias_s = (const float*)(smem + U_BIAS);

    int cnt = 0, prev_it = -1;
    float4 f[8];
    int it = blockIdx.x;
    if (it < ntiles) {
        const float* Ab = A + (size_t)it * 128 * 128;
        #pragma unroll
        for (int u = 0; u < 4; u++) {
            int g = tid + u * 512;
            int r = g >> 4, kg = (g & 15) << 3;
            f[2*u]   = *(const float4*)(Ab + (size_t)r * 128 + kg);
            f[2*u+1] = *(const float4*)(Ab + (size_t)r * 128 + kg + 4);
        }
    }
    for (; it < ntiles; it += gridDim.x, cnt++) {
        const int b = cnt & 1;
        char* abuf = smem + (b ? PT_A1 : PT_A0);
        #pragma unroll
        for (int u = 0; u < 4; u++) {
            int g = tid + u * 512;
            int r = g >> 4, kg = (g & 15) << 3;
            float v8[8];
            v8[0]=f[2*u].x; v8[1]=f[2*u].y; v8[2]=f[2*u].z; v8[3]=f[2*u].w;
            v8[4]=f[2*u+1].x; v8[5]=f[2*u+1].y; v8[6]=f[2*u+1].z; v8[7]=f[2*u+1].w;
            if (padA) {
                int grow = it * 128 + r;
                if ((grow & 63) >= lengths[grow >> 6]) {
                    #pragma unroll
                    for (int d = 0; d < 8; d++) v8[d] = -1.f;
                }
            }
            uint4 Hv, Lv; split8(v8, Hv, Lv);
            uint32_t o = tile_off(r, kg);
            *(uint4*)(abuf + o) = Hv;
            *(uint4*)(abuf + 32768 + o) = Lv;
        }
        __syncthreads();
        if (wid == 0 && elect1()) {
            asm volatile("fence.proxy.async.shared::cta;" ::: "memory");
            asm volatile("tcgen05.fence::after_thread_sync;" ::: "memory");
            uint64_t ah = mk_desc(sb + (b ? PT_A1 : PT_A0));
            uint64_t al = mk_desc(sb + (b ? PT_A1 : PT_A0) + 32768);
            uint32_t d = tmem + b * 128;
            #pragma unroll
            for (int s = 0; s < 8; s++) {
                uint64_t doff = (uint64_t)(((s >> 2) << 10) + ((s & 3) << 1));
                mma_ss(d, ah + doff, bh + doff, s > 0 ? 1u : 0u);
                mma_ss(d, ah + doff, bl + doff, 1u);
                mma_ss(d, al + doff, bh + doff, 1u);
            }
            asm volatile("tcgen05.commit.cta_group::1.mbarrier::arrive::one.shared::cluster.b64 [%0];"
                         :: "r"(sb + 8 + b * 8) : "memory");
        }
        {
            int nit = it + gridDim.x;
            if (nit < ntiles) {
                const float* Ab2 = A + (size_t)nit * 128 * 128;
                #pragma unroll
                for (int u = 0; u < 4; u++) {
                    int g = tid + u * 512;
                    int r = g >> 4, kg = (g & 15) << 3;
                    f[2*u]   = *(const float4*)(Ab2 + (size_t)r * 128 + kg);
                    f[2*u+1] = *(const float4*)(Ab2 + (size_t)r * 128 + kg + 4);
                }
            }
        }
        if (cnt > 0) {
            int pc = cnt - 1, pb = pc & 1;
            MBAR_WAIT(sb + 8 + pb * 8, (pc >> 1) & 1);
            asm volatile("tcgen05.fence::after_thread_sync;" ::: "memory");
            float v[32]; uint32_t vr[32];
            LDTM_X32(vr, tmem + pb * 128 + nh * 32);
            asm volatile("tcgen05.wait::ld.sync.aligned;" ::: "memory");
            #pragma unroll
            for (int j = 0; j < 32; j++) v[j] = __uint_as_float(vr[j]);
            asm volatile("tcgen05.fence::before_thread_sync;" ::: "memory");
            epi_tile(v, smem, smem + (pb ? PT_A1 : PT_A0), mode, prev_it * 128, nh, rl, wid, lid,
                     bias_s, res, pos, C, ldC, n0);
        }
        prev_it = it;
    }
    if (cnt > 0) {
        int pc = cnt - 1, pb = pc & 1;
        MBAR_WAIT(sb + 8 + pb * 8, (pc >> 1) & 1);
        asm volatile("tcgen05.fence::after_thread_sync;" ::: "memory");
        float v[32]; uint32_t vr[32];
        LDTM_X32(vr, tmem + pb * 128 + nh * 32);
        asm volatile("tcgen05.wait::ld.sync.aligned;" ::: "memory");
        #pragma unroll
        for (int j = 0; j < 32; j++) v[j] = __uint_as_float(vr[j]);
        asm volatile("tcgen05.fence::before_thread_sync;" ::: "memory");
        epi_tile(v, smem, smem + (pb ? PT_A0 : PT_A1), mode, prev_it * 128, nh, rl, wid, lid,
                 bias_s, res, pos, C, ldC, n0);
    }
    __syncthreads();
    if (tid == 0) {
        asm volatile("mbarrier.inval.shared.b64 [%0];" :: "r"(sb + 8) : "memory");
        asm volatile("mbarrier.inval.shared.b64 [%0];" :: "r"(sb + 16) : "memory");
    }
    __syncthreads();
    if (wid == 0) {
        asm volatile("tcgen05.relinquish_alloc_permit.cta_group::1.sync.aligned;");
        asm volatile("tcgen05.dealloc.cta_group::1.sync.aligned.b32 %0, %1;" :: "r"(tmem), "r"(256u));
    }
#endif
}

// ============== persistent K=128 NT=2 fused GEMM (R11 form) ===========
__global__ __launch_bounds__(512, 1) void tc_pgemm2(
    const float* __restrict__ A, float* __restrict__ C,
    const float* __restrict__ b0p, const float* __restrict__ b1p,
    int ntiles, int mode, int tileB)
{
#if TC_OK
    extern __shared__ char smem_raw[];
    uint32_t sb0 = smem_u32(smem_raw);
    uint32_t sb = (sb0 + 1023) & ~1023u;
    char* smem = smem_raw + (sb - sb0);
    const int tid = threadIdx.x;
    const int wid = tid >> 5, lid = tid & 31;
    const int nh = wid >> 2;
    const int rl = ((wid & 3) << 5) + lid;

    if (wid == 0)
        asm volatile("tcgen05.alloc.cta_group::1.sync.aligned.shared::cta.b32 [%0], %1;"
                     :: "r"(sb), "r"(512u) : "memory");
    if (tid == 0) {
        asm volatile("mbarrier.init.shared.b64 [%0], %1;" :: "r"(sb + 8), "r"(1u) : "memory");
        asm volatile("mbarrier.init.shared.b64 [%0], %1;" :: "r"(sb + 16), "r"(1u) : "memory");
    }
    if (tid < 128) ((float*)(smem + U_BIAS))[tid] = b0p[tid];
    else if (tid < 256) ((float*)(smem + U_BIAS))[tid] = b1p[tid - 128];
    for (int nt = 0; nt < 2; nt++) {
        const uint4* sh = g_wimg_hi + (size_t)(tileB + nt) * 2048;
        const uint4* sl = g_wimg_lo + (size_t)(tileB + nt) * 2048;
        uint4* dh = (uint4*)(smem + P2_B + nt * 65536);
        uint4* dl = (uint4*)(smem + P2_B + nt * 65536 + 32768);
        #pragma unroll
        for (int u = 0; u < 4; u++) { dh[tid + u*512] = sh[tid + u*512]; dl[tid + u*512] = sl[tid + u*512]; }
    }
    __syncthreads();
    uint32_t tmem;
    asm volatile("ld.shared.b32 %0, [%1];" : "=r"(tmem) : "r"(sb));
    const float* bias_s = (const float*)(smem + U_BIAS);
    char* scr16 = smem + P2_SCR;

    int cnt = 0, prev_it = -1;
    float4 f[8];
    int it = blockIdx.x;
    if (it < ntiles) {
        const float* Ab = A + (size_t)it * 128 * 128;
        #pragma unroll
        for (int u = 0; u < 4; u++) {
            int g = tid + u * 512;
            int r = g >> 4, kg = (g & 15) << 3;
            f[2*u]   = *(const float4*)(Ab + (size_t)r * 128 + kg);
            f[2*u+1] = *(const float4*)(Ab + (size_t)r * 128 + kg + 4);
        }
    }
    for (; it < ntiles; it += gridDim.x, cnt++) {
        const int b = cnt & 1;
        if (cnt > 0) {
            int pc = cnt - 1;
            MBAR_WAIT(sb + 8 + (pc & 1) * 8, (pc >> 1) & 1);
        }
        #pragma unroll
        for (int u = 0; u < 4; u++) {
            int g = tid + u * 512;
            int r = g >> 4, kg = (g & 15) << 3;
            float v8[8];
            v8[0]=f[2*u].x; v8[1]=f[2*u].y; v8[2]=f[2*u].z; v8[3]=f[2*u].w;
            v8[4]=f[2*u+1].x; v8[5]=f[2*u+1].y; v8[6]=f[2*u+1].z; v8[7]=f[2*u+1].w;
            uint4 Hv, Lv; split8(v8, Hv, Lv);
            uint32_t o = tile_off(r, kg);
            *(uint4*)(smem + P2_A + o) = Hv;
            *(uint4*)(smem + P2_A + 32768 + o) = Lv;
        }
        __syncthreads();
        if (wid == 0 && elect1()) {
            asm volatile("fence.proxy.async.shared::cta;" ::: "memory");
            asm volatile("tcgen05.fence::after_thread_sync;" ::: "memory");
            uint64_t ah = mk_desc(sb + P2_A), al = mk_desc(sb + P2_A + 32768);
            #pragma unroll
            for (int nt = 0; nt < 2; nt++) {
                uint64_t bhd = mk_desc(sb + P2_B + nt * 65536);
                uint64_t bld = mk_desc(sb + P2_B + nt * 65536 + 32768);
                uint32_t d = tmem + b * 256 + nt * 128;
                #pragma unroll
                for (int s = 0; s < 8; s++) {
                    uint64_t doff = (uint64_t)(((s >> 2) << 10) + ((s & 3) << 1));
                    mma_ss(d, ah + doff, bhd + doff, s > 0 ? 1u : 0u);
                    mma_ss(d, ah + doff, bld + doff, 1u);
                    mma_ss(d, al + doff, bhd + doff, 1u);
                }
            }
            asm volatile("tcgen05.commit.cta_group::1.mbarrier::arrive::one.shared::cluster.b64 [%0];"
                         :: "r"(sb + 8 + b * 8) : "memory");
        }
        {
            int nit = it + gridDim.x;
            if (nit < ntiles) {
                const float* Ab2 = A + (size_t)nit * 128 * 128;
                #pragma unroll
                for (int u = 0; u < 4; u++) {
                    int g = tid + u * 512;
                    int r = g >> 4, kg = (g & 15) << 3;
                    f[2*u]   = *(const float4*)(Ab2 + (size_t)r * 128 + kg);
                    f[2*u+1] = *(const float4*)(Ab2 + (size_t)r * 128 + kg + 4);
                }
            }
        }
        if (cnt > 0) {
            int pb = (cnt - 1) & 1;
            asm volatile("tcgen05.fence::after_thread_sync;" ::: "memory");
            #pragma unroll
            for (int nt = 0; nt < 2; nt++) {
                float v[32]; uint32_t vr[32];
                LDTM_X32(vr, tmem + pb * 256 + nt * 128 + nh * 32);
                asm volatile("tcgen05.wait::ld.sync.aligned;" ::: "memory");
                #pragma unroll
                for (int j = 0; j < 32; j++) v[j] = __uint_as_float(vr[j]);
                asm volatile("tcgen05.fence::before_thread_sync;" ::: "memory");
                epi_tile_lite(v, scr16, mode, prev_it * 128, nh, rl, tid,
                              bias_s + nt * 128, C, 256, nt * 128);
            }
        }
        prev_it = it;
    }
    if (cnt > 0) {
        int pc = cnt - 1, pb = pc & 1;
        MBAR_WAIT(sb + 8 + pb * 8, (pc >> 1) & 1);
        asm volatile("tcgen05.fence::after_thread_sync;" ::: "memory");
        #pragma unroll
        for (int nt = 0; nt < 2; nt++) {
            float v[32]; uint32_t vr[32];
            LDTM_X32(vr, tmem + pb * 256 + nt * 128 + nh * 32);
            asm volatile("tcgen05.wait::ld.sync.aligned;" ::: "memory");
            #pragma unroll
            for (int j = 0; j < 32; j++) v[j] = __uint_as_float(vr[j]);
            asm volatile("tcgen05.fence::before_thread_sync;" ::: "memory");
            epi_tile_lite(v, scr16, mode, prev_it * 128, nh, rl, tid,
                          bias_s + nt * 128, C, 256, nt * 128);
        }
    }
    __syncthreads();
    if (tid == 0) {
        asm volatile("mbarrier.inval.shared.b64 [%0];" :: "r"(sb + 8) : "memory");
        asm volatile("mbarrier.inval.shared.b64 [%0];" :: "r"(sb + 16) : "memory");
    }
    __syncthreads();
    if (wid == 0) {
        asm volatile("tcgen05.relinquish_alloc_permit.cta_group::1.sync.aligned;");
        asm volatile("tcgen05.dealloc.cta_group::1.sync.aligned.b32 %0, %1;" :: "r"(tmem), "r"(512u));
    }
#endif
}

// ============== persistent fused FFN: x -> relu(xW1+b1) -> W2+b2 +res, LN ====
#if TC_OK
__device__ __forceinline__ void pf_loadB(char* smem, uint32_t boff, int tile, int tid) {
    const uint4* sh = g_wimg_hi + (size_t)tile * 2048;
    const uint4* sl = g_wimg_lo + (size_t)tile * 2048;
    uint4* dh = (uint4*)(smem + boff);
    uint4* dl = (uint4*)(smem + boff + 32768);
    #pragma unroll
    for (int u = 0; u < 4; u++) { dh[tid + u*512] = sh[tid + u*512]; dl[tid + u*512] = sl[tid + u*512]; }
}
__device__ __forceinline__ void pf_mma1(uint32_t sb, uint32_t tmem, int wid) {
    if (wid == 0 && elect1()) {
        asm volatile("fence.proxy.async.shared::cta;" ::: "memory");
        asm volatile("tcgen05.fence::after_thread_sync;" ::: "memory");
        uint64_t ah = mk_desc(sb + PF_A), al = mk_desc(sb + PF_A + 32768);
        #pragma unroll
        for (int nt = 0; nt < 2; nt++) {
            uint64_t bh = mk_desc(sb + (nt ? PF_B1 : PF_B0));
            uint64_t bl = mk_desc(sb + (nt ? PF_B1 : PF_B0) + 32768);
            uint32_t d = tmem + nt * 128;
            #pragma unroll
            for (int s = 0; s < 8; s++) {
                uint64_t doff = (uint64_t)(((s >> 2) << 10) + ((s & 3) << 1));
                mma_ss(d, ah + doff, bh + doff, s > 0 ? 1u : 0u);
                mma_ss(d, ah + doff, bl + doff, 1u);
                mma_ss(d, al + doff, bh + doff, 1u);
            }
        }
        asm volatile("tcgen05.commit.cta_group::1.mbarrier::arrive::one.shared::cluster.b64 [%0];"
                     :: "r"(sb + 8) : "memory");
    }
}
__device__ __forceinline__ void pf_mma2(uint32_t sb, uint32_t tmem, int wid, int fresh) {
    if (wid == 0 && elect1()) {
        asm volatile("fence.proxy.async.shared::cta;" ::: "memory");
        asm volatile("tcgen05.fence::after_thread_sync;" ::: "memory");
        uint64_t ah = mk_desc(sb + PF_A), al = mk_desc(sb + PF_A + 32768);
        uint64_t bh = mk_desc(sb + PF_B1), bl = mk_desc(sb + PF_B1 + 32768);
        uint32_t d = tmem + 256;
        #pragma unroll
        for (int s = 0; s < 8; s++) {
            uint64_t doff = (uint64_t)(((s >> 2) << 10) + ((s & 3) << 1));
            mma_ss(d, ah + doff, bh + doff, (fresh && s == 0) ? 0u : 1u);
            mma_ss(d, ah + doff, bl + doff, 1u);
            mma_ss(d, al + doff, bh + doff, 1u);
        }
        asm volatile("tcgen05.commit.cta_group::1.mbarrier::arrive::one.shared::cluster.b64 [%0];"
                     :: "r"(sb + 8) : "memory");
    }
}
#endif

__global__ __launch_bounds__(512, 1) void tc_pffn(
    float* __restrict__ X, int ntiles, int tW1, int tW2,
    const float* __restrict__ b1p, const float* __restrict__ b2p,
    const float* __restrict__ lns, const float* __restrict__ lnb)
{
#if TC_OK
    extern __shared__ char smem_raw[];
    uint32_t sb0 = smem_u32(smem_raw);
    uint32_t sb = (sb0 + 1023) & ~1023u;
    char* smem = smem_raw + (sb - sb0);
    const int tid = threadIdx.x;
    const int wid = tid >> 5, lid = tid & 31;
    const int nh = wid >> 2;
    const int rl = ((wid & 3) << 5) + lid;
    const int bc = nh * 32;

    if (wid == 0)
        asm volatile("tcgen05.alloc.cta_group::1.sync.aligned.shared::cta.b32 [%0], %1;"
                     :: "r"(sb), "r"(512u) : "memory");
    if (tid == 0)
        asm volatile("mbarrier.init.shared.b64 [%0], %1;" :: "r"(sb + 8), "r"(1u) : "memory");
    if (tid < 256) ((float*)(smem + U_BIAS))[tid] = b1p[tid];
    if (tid < 128) {
        ((float*)(smem + U_B2 ))[tid] = b2p[tid];
        ((float*)(smem + U_LNS))[tid] = lns[tid];
        ((float*)(smem + U_LNB))[tid] = lnb[tid];
    }
    pf_loadB(smem, PF_B0, tW1, tid);       // W1a resident
    pf_loadB(smem, PF_B1, tW1 + 1, tid);   // W1b initially
    __syncthreads();
    uint32_t tmem;
    asm volatile("ld.shared.b32 %0, [%1];" : "=r"(tmem) : "r"(sb));
    const float* b1s = (const float*)(smem + U_BIAS);
    char* scr16 = smem + PF_SCR;
    int mc = 0;

    for (int it = blockIdx.x; it < ntiles; it += gridDim.x) {
        const int t0r = it * 128;
        // stage x -> A
        {
            const float* Ab = X + (size_t)t0r * 128;
            #pragma unroll
            for (int u = 0; u < 4; u++) {
                int g = tid + u * 512;
                int r = g >> 4, kg = (g & 15) << 3;
                float4 f0 = *(const float4*)(Ab + (size_t)r * 128 + kg);
                float4 f1 = *(const float4*)(Ab + (size_t)r * 128 + kg + 4);
                float v8[8] = {f0.x,f0.y,f0.z,f0.w,f1.x,f1.y,f1.z,f1.w};
                uint4 Hv, Lv; split8(v8, Hv, Lv);
                uint32_t o = tile_off(r, kg);
                *(uint4*)(smem + PF_A + o) = Hv;
                *(uint4*)(smem + PF_A + 32768 + o) = Lv;
            }
        }
        __syncthreads();
        pf_mma1(sb, tmem, wid);                       // h = x@W1 -> T[0:256)
        MBAR_WAIT(sb + 8, mc & 1); mc++;
        asm volatile("tcgen05.fence::after_thread_sync;" ::: "memory");
        // FFN2 chunk 0: h0 (T[0:128)) vs W2a
        float v[32]; uint32_t vr[32];
        LDTM_X32(vr, tmem + nh * 32);
        asm volatile("tcgen05.wait::ld.sync.aligned;" ::: "memory");
        #pragma unroll
        for (int j = 0; j < 32; j++) v[j] = fmaxf(__uint_as_float(vr[j]) + b1s[bc + j], 0.f);
        asm volatile("tcgen05.fence::before_thread_sync;" ::: "memory");
        #pragma unroll
        for (int u = 0; u < 4; u++) {
            uint4 Hv, Lv; split8(v + u * 8, Hv, Lv);
            uint32_t o = tile_off(rl, bc + u * 8);
            *(uint4*)(smem + PF_A + o) = Hv;
            *(uint4*)(smem + PF_A + 32768 + o) = Lv;
        }
        pf_loadB(smem, PF_B1, tW2, tid);              // W2a (B1 free: MMA1 done)
        __syncthreads();
        pf_mma2(sb, tmem, wid, 1);
        MBAR_WAIT(sb + 8, mc & 1); mc++;
        asm volatile("tcgen05.fence::after_thread_sync;" ::: "memory");
        // FFN2 chunk 1: h1 (T[128:256)) vs W2b
        LDTM_X32(vr, tmem + 128 + nh * 32);
        asm volatile("tcgen05.wait::ld.sync.aligned;" ::: "memory");
        #pragma unroll
        for (int j = 0; j < 32; j++) v[j] = fmaxf(__uint_as_float(vr[j]) + b1s[128 + bc + j], 0.f);
        asm volatile("tcgen05.fence::before_thread_sync;" ::: "memory");
        #pragma unroll
        for (int u = 0; u < 4; u++) {
            uint4 Hv, Lv; split8(v + u * 8, Hv, Lv);
            uint32_t o = tile_off(rl, bc + u * 8);
            *(uint4*)(smem + PF_A + o) = Hv;
            *(uint4*)(smem + PF_A + 32768 + o) = Lv;
        }
        pf_loadB(smem, PF_B1, tW2 + 1, tid);          // W2b
        __syncthreads();
        pf_mma2(sb, tmem, wid, 0);
        MBAR_WAIT(sb + 8, mc & 1); mc++;
        asm volatile("tcgen05.fence::after_thread_sync;" ::: "memory");
        // epilogue: y + b2 + residual(X) + LN -> X
        LDTM_X32(vr, tmem + 256 + nh * 32);
        asm volatile("tcgen05.wait::ld.sync.aligned;" ::: "memory");
        #pragma unroll
        for (int j = 0; j < 32; j++) v[j] = __uint_as_float(vr[j]) + ((const float*)(smem + U_B2))[bc + j];
        asm volatile("tcgen05.fence::before_thread_sync;" ::: "memory");
        pf_loadB(smem, PF_B1, tW1 + 1, tid);          // restore W1b for next tile
        // residual via 4-phase scratch
        #pragma unroll
        for (int p = 0; p < 4; p++) {
            #pragma unroll
            for (int e = 0; e < 2; e++) {
                int id = tid + e * 512;
                int r32 = id >> 5, c = id & 31;
                *(float4*)(scr16 + scr_off(r32, c)) =
                    *(const float4*)(X + (size_t)(t0r + p * 32 + r32) * 128 + c * 4);
            }
            __syncthreads();
            if ((rl >> 5) == p) {
                #pragma unroll
                for (int j4 = 0; j4 < 8; j4++) {
                    float4 r4 = *(const float4*)(scr16 + scr_off(rl & 31, (bc >> 2) + j4));
                    v[4*j4+0] += r4.x; v[4*j4+1] += r4.y; v[4*j4+2] += r4.z; v[4*j4+3] += r4.w;
                }
            }
            __syncthreads();
        }
        // LN
        {
            float s = 0.f, qq = 0.f;
            #pragma unroll
            for (int j = 0; j < 32; j++) { s += v[j]; qq += v[j] * v[j]; }
            ((float*)(smem + U_PSUM))[nh * 128 + rl] = s;
            ((float*)(smem + U_PSQ ))[nh * 128 + rl] = qq;
            __syncthreads();
            float ts = 0.f, tq = 0.f;
            #pragma unroll
            for (int g = 0; g < 4; g++) {
                ts += ((float*)(smem + U_PSUM))[g * 128 + rl];
                tq += ((float*)(smem + U_PSQ ))[g * 128 + rl];
            }
            __syncthreads();
            float mean = ts * (1.f / 128.f);
            float rstd = rsqrtf(tq * (1.f / 128.f) - mean * mean + 1e-5f);
            const float* Ls = (const float*)(smem + U_LNS);
            const float* Lb = (const float*)(smem + U_LNB);
            #pragma unroll
            for (int j = 0; j < 32; j++) v[j] = (v[j] - mean) * rstd * Ls[bc + j] + Lb[bc + j];
        }
        // store via 4-phase scratch
        #pragma unroll
        for (int p = 0; p < 4; p++) {
            if ((rl >> 5) == p) {
                #pragma unroll
                for (int j4 = 0; j4 < 8; j4++)
                    *(float4*)(scr16 + scr_off(rl & 31, (bc >> 2) + j4)) =
                        make_float4(v[4*j4], v[4*j4+1], v[4*j4+2], v[4*j4+3]);
            }
            __syncthreads();
            #pragma unroll
            for (int e = 0; e < 2; e++) {
                int id = tid + e * 512;
                int r32 = id >> 5, c = id & 31;
                *(float4*)(X + (size_t)(t0r + p * 32 + r32) * 128 + c * 4) =
                    *(const float4*)(scr16 + scr_off(r32, c));
            }
            __syncthreads();
        }
    }
    __syncthreads();
    if (tid == 0)
        asm volatile("mbarrier.inval.shared.b64 [%0];" :: "r"(sb + 8) : "memory");
    __syncthreads();
    if (wid == 0) {
        asm volatile("tcgen05.relinquish_alloc_permit.cta_group::1.sync.aligned;");
        asm volatile("tcgen05.dealloc.cta_group::1.sync.aligned.b32 %0, %1;" :: "r"(tmem), "r"(512u));
    }
#endif
}

// ======== generic GEMM: 2D grid, blockIdx.y = N-tile =========
__global__ __launch_bounds__(512, 1) void tc_gemm(
    const float* __restrict__ A, float* __restrict__ C,
    const float* __restrict__ bias0, const float* __restrict__ bias1,
    const float* __restrict__ bias2,
    const float* __restrict__ res, const float* __restrict__ lns,
    const float* __restrict__ lnb,
    int KC, int NT, int mode, int tile0)
{
#if TC_OK
    extern __shared__ char smem_raw[];
    uint32_t sb0 = smem_u32(smem_raw);
    uint32_t sb = (sb0 + 1023) & ~1023u;
    char* smem = smem_raw + (sb - sb0);
    const int tid = threadIdx.x;
    const int wid = tid >> 5, lid = tid & 31;
    const int m0 = blockIdx.x * 128;
    const int nt = blockIdx.y;
    const int Ktot = KC * 128;
    const int N = NT * 128;
    const int nh = wid >> 2;
    const int rl = ((wid & 3) << 5) + lid;

    if (wid == 0)
        asm volatile("tcgen05.alloc.cta_group::1.sync.aligned.shared::cta.b32 [%0], %1;"
                     :: "r"(sb), "r"(128u) : "memory");
    if (tid == 0)
        asm volatile("mbarrier.init.shared.b64 [%0], %1;" :: "r"(sb + 8), "r"(1u) : "memory");
    {
        const float* bN = (nt == 0) ? bias0 : ((nt == 1) ? bias1 : bias2);
        if (tid < 128) {
            ((float*)(smem + U_BIAS))[tid] = bN[tid];
            if (mode >= 2) {
                ((float*)(smem + U_LNS))[tid] = lns[tid];
                ((float*)(smem + U_LNB))[tid] = lnb[tid];
            }
        }
    }
    __syncthreads();
    uint32_t tmem;
    asm volatile("ld.shared.b32 %0, [%1];" : "=r"(tmem) : "r"(sb));

    for (int kc = 0; kc < KC; kc++) {
        if (kc > 0) MBAR_WAIT(sb + 8, (kc - 1) & 1);
        const float* Ab = A + (size_t)m0 * Ktot + kc * 128;
        float4 f[8];
        #pragma unroll
        for (int u = 0; u < 4; u++) {
            int g = tid + u * 512;
            int r = g >> 4, kg = (g & 15) << 3;
            f[2*u]   = *(const float4*)(Ab + (size_t)r * Ktot + kg);
            f[2*u+1] = *(const float4*)(Ab + (size_t)r * Ktot + kg + 4);
        }
        #pragma unroll
        for (int u = 0; u < 4; u++) {
            int g = tid + u * 512;
            int r = g >> 4, kg = (g & 15) << 3;
            float v8[8];
            v8[0]=f[2*u].x; v8[1]=f[2*u].y; v8[2]=f[2*u].z; v8[3]=f[2*u].w;
            v8[4]=f[2*u+1].x; v8[5]=f[2*u+1].y; v8[6]=f[2*u+1].z; v8[7]=f[2*u+1].w;
            uint4 Hv, Lv; split8(v8, Hv, Lv);
            uint32_t o = tile_off(r, kg);
            *(uint4*)(smem + SM_AHI + o) = Hv;
            *(uint4*)(smem + SM_ALO + o) = Lv;
        }
        {
            int tI = tile0 + kc * NT + nt;
            const uint4* sh = g_wimg_hi + (size_t)tI * 2048;
            const uint4* sl = g_wimg_lo + (size_t)tI * 2048;
            uint4* dh = (uint4*)(smem + SM_B);
            uint4* dl = (uint4*)(smem + SM_B + 32768);
            #pragma unroll
            for (int u = 0; u < 4; u++) { dh[tid + u*512] = sh[tid + u*512]; dl[tid + u*512] = sl[tid + u*512]; }
        }
        __syncthreads();
        if (wid == 0 && elect1()) {
            asm volatile("fence.proxy.async.shared::cta;" ::: "memory");
            uint64_t ah = mk_desc(sb + SM_AHI), al = mk_desc(sb + SM_ALO);
            uint64_t bhd = mk_desc(sb + SM_B), bld = mk_desc(sb + SM_B + 32768);
            #pragma unroll
            for (int s = 0; s < 8; s++) {
                uint64_t doff = (uint64_t)(((s >> 2) << 10) + ((s & 3) << 1));
                uint32_t first = (kc == 0 && s == 0) ? 0u : 1u;
                mma_ss(tmem, ah + doff, bhd + doff, first);
                mma_ss(tmem, ah + doff, bld + doff, 1u);
                mma_ss(tmem, al + doff, bhd + doff, 1u);
            }
            asm volatile("tcgen05.commit.cta_group::1.mbarrier::arrive::one.shared::cluster.b64 [%0];"
                         :: "r"(sb + 8) : "memory");
        }
    }
    MBAR_WAIT(sb + 8, (KC - 1) & 1);
    asm volatile("tcgen05.fence::after_thread_sync;" ::: "memory");
    {
        float v[32]; uint32_t vr[32];
        LDTM_X32(vr, tmem + nh * 32);
        asm volatile("tcgen05.wait::ld.sync.aligned;" ::: "memory");
        #pragma unroll
        for (int j = 0; j < 32; j++) v[j] = __uint_as_float(vr[j]);
        asm volatile("tcgen05.fence::before_thread_sync;" ::: "memory");
        epi_tile(v, smem, smem + SM_AHI, mode, m0, nh, rl, wid, lid,
                 (const float*)(smem + U_BIAS), res, nullptr, C, N, nt * 128);
    }
    __syncthreads();
    if (tid == 0)
        asm volatile("mbarrier.inval.shared.b64 [%0];" :: "r"(sb + 8) : "memory");
    __syncthreads();
    if (wid == 0) {
        asm volatile("tcgen05.relinquish_alloc_permit.cta_group::1.sync.aligned;");
        asm volatile("tcgen05.dealloc.cta_group::1.sync.aligned.b32 %0, %1;" :: "r"(tmem), "r"(128u));
    }
#endif
}

// --------- temporal attention: one block per sequence ----
#define ROWF 33
__global__ __launch_bounds__(512) void attn_seq_kernel(
    const float* __restrict__ Q, const float* __restrict__ Km,
    const float* __restrict__ Vm, float* __restrict__ O,
    const int* __restrict__ lengths, int ldkv)
{
    extern __shared__ float4 smf[];
    float4* ks4 = smf;
    float4* vs4 = smf + 64 * ROWF;
    float4* qm4 = smf + 2 * 64 * ROWF;
    const int n = blockIdx.x, tid = threadIdx.x;
    const int head = tid >> 6, i = tid & 63;
    const int ldkv4 = ldkv >> 2;
    const float4* Kb = (const float4*)(Km + (size_t)n * T_ * ldkv);
    const float4* Vb = (const float4*)(Vm + (size_t)n * T_ * ldkv);
    const float4* Qb = (const float4*)(Q  + (size_t)n * T_ * H_);
    #pragma unroll
    for (int u = 0; u < 4; u++) {
        int idx = tid + u * 512;
        int r = idx >> 5, c = idx & 31;
        ks4[r * ROWF + c] = Kb[r * ldkv4 + c];
        vs4[r * ROWF + c] = Vb[r * ldkv4 + c];
        qm4[r * ROWF + c] = Qb[r * 32 + c];
    }
    const int len = lengths[n];
    const int myv = (i < len);
    __syncthreads();
    const int c0 = head * 4;
    float4 q0 = qm4[i * ROWF + c0],     q1 = qm4[i * ROWF + c0 + 1],
           q2 = qm4[i * ROWF + c0 + 2], q3 = qm4[i * ROWF + c0 + 3];
    float m = -1e30f, s = 0.f, acc[16];
    #pragma unroll
    for (int d = 0; d < 16; d++) acc[d] = 0.f;
    for (int j = 0; j < len; j++) {
        float sc;
        if (myv) {
            float4 a0 = ks4[j*ROWF+c0], a1 = ks4[j*ROWF+c0+1],
                   a2 = ks4[j*ROWF+c0+2], a3 = ks4[j*ROWF+c0+3];
            float d = a0.x*q0.x + a0.y*q0.y + a0.z*q0.z + a0.w*q0.w
                    + a1.x*q1.x + a1.y*q1.y + a1.z*q1.z + a1.w*q1.w
                    + a2.x*q2.x + a2.y*q2.y + a2.z*q2.z + a2.w*q2.w
                    + a3.x*q3.x + a3.y*q3.y + a3.z*q3.z + a3.w*q3.w;
            sc = d * SCALE_;
        } else sc = -1e9f;
        float w;
        if (sc > m) {
            float c = __expf(m - sc);
            s = s * c + 1.f;
            #pragma unroll
            for (int d = 0; d < 16; d++) acc[d] *= c;
            m = sc; w = 1.f;
        } else { w = __expf(sc - m); s += w; }
        float4 b0 = vs4[j*ROWF+c0], b1 = vs4[j*ROWF+c0+1],
               b2 = vs4[j*ROWF+c0+2], b3 = vs4[j*ROWF+c0+3];
        acc[0]  += w*b0.x; acc[1]  += w*b0.y; acc[2]  += w*b0.z; acc[3]  += w*b0.w;
        acc[4]  += w*b1.x; acc[5]  += w*b1.y; acc[6]  += w*b1.z; acc[7]  += w*b1.w;
        acc[8]  += w*b2.x; acc[9]  += w*b2.y; acc[10] += w*b2.z; acc[11] += w*b2.w;
        acc[12] += w*b3.x; acc[13] += w*b3.y; acc[14] += w*b3.z; acc[15] += w*b3.w;
    }
    if (!myv) {
        for (int j = len; j < T_; j++) {
            s += 1.f;
            float4 b0 = vs4[j*ROWF+c0], b1 = vs4[j*ROWF+c0+1],
                   b2 = vs4[j*ROWF+c0+2], b3 = vs4[j*ROWF+c0+3];
            acc[0]  += b0.x; acc[1]  += b0.y; acc[2]  += b0.z; acc[3]  += b0.w;
            acc[4]  += b1.x; acc[5]  += b1.y; acc[6]  += b1.z; acc[7]  += b1.w;
            acc[8]  += b2.x; acc[9]  += b2.y; acc[10] += b2.z; acc[11] += b2.w;
            acc[12] += b3.x; acc[13] += b3.y; acc[14] += b3.z; acc[15] += b3.w;
        }
    }
    float inv = 1.f / s;
    __syncthreads();
    qm4[i*ROWF+c0]   = make_float4(acc[0]*inv,  acc[1]*inv,  acc[2]*inv,  acc[3]*inv);
    qm4[i*ROWF+c0+1] = make_float4(acc[4]*inv,  acc[5]*inv,  acc[6]*inv,  acc[7]*inv);
    qm4[i*ROWF+c0+2] = make_float4(acc[8]*inv,  acc[9]*inv,  acc[10]*inv, acc[11]*inv);
    qm4[i*ROWF+c0+3] = make_float4(acc[12]*inv, acc[13]*inv, acc[14]*inv, acc[15]*inv);
    __syncthreads();
    float4* Ob = (float4*)(O + (size_t)n * T_ * H_);
    #pragma unroll
    for (int u = 0; u < 4; u++) {
        int idx = tid + u * 512;
        int r = idx >> 5, c = idx & 31;
        Ob[idx] = qm4[r * ROWF + c];
    }
}

// ---------------- spatial attention ----------------
template <int L, bool SPATIAL>
__global__ __launch_bounds__(L) void attn_kernel(
    const float* __restrict__ Q, const float* __restrict__ Km,
    const float* __restrict__ Vm, float* __restrict__ O,
    const int* __restrict__ lengths, int ld)
{
    const int head = blockIdx.x, n = blockIdx.y, i = threadIdx.x;
    __shared__ float ks[L][DHP], vs[L][DHP], qs[L][DHP];
    __shared__ int vm[L];
    const size_t rowbase = (size_t)n * L;
    const int coff = head * DH_;
    #pragma unroll
    for (int x = 0; x < 4; x++) {
        int idx = x * L + i;
        int j = idx >> 2, q = (idx & 3) * 4;
        *(float4*)&ks[j][q] = *(const float4*)(Km + (rowbase + j) * ld + coff + q);
        *(float4*)&vs[j][q] = *(const float4*)(Vm + (rowbase + j) * ld + coff + q);
        *(float4*)&qs[j][q] = *(const float4*)(Q  + (rowbase + j) * ld + coff + q);
    }
    int len = 0, myv;
    if (SPATIAL) { myv = (lengths[n * S_ + i] > 0) ? 1 : 0; vm[i] = myv; }
    else         { len = lengths[n]; myv = (i < len) ? 1 : 0; }
    __syncthreads();
    float qr[DH_];
    #pragma unroll
    for (int d = 0; d < DH_; d++) qr[d] = qs[i][d];

    float m = -1e30f, s = 0.f, acc[DH_];
    #pragma unroll
    for (int dd = 0; dd < DH_; dd++) acc[dd] = 0.f;

    const int jmax = SPATIAL ? L : len;
    for (int j = 0; j < jmax; j++) {
        if (SPATIAL && !vm[j]) continue;
        float sc;
        if (myv) {
            const float4* kp = (const float4*)&ks[j][0];
            float4 a0 = kp[0], a1 = kp[1], a2 = kp[2], a3 = kp[3];
            float d = a0.x*qr[0] + a0.y*qr[1] + a0.z*qr[2] + a0.w*qr[3]
                    + a1.x*qr[4] + a1.y*qr[5] + a1.z*qr[6] + a1.w*qr[7]
                    + a2.x*qr[8] + a2.y*qr[9] + a2.z*qr[10] + a2.w*qr[11]
                    + a3.x*qr[12] + a3.y*qr[13] + a3.z*qr[14] + a3.w*qr[15];
            sc = d * SCALE_;
        } else sc = -1e9f;
        float w;
        if (sc > m) {
            float c = __expf(m - sc);
            s = s * c + 1.f;
            #pragma unroll
            for (int dd = 0; dd < DH_; dd++) acc[dd] *= c;
            m = sc; w = 1.f;
        } else {
            w = __expf(sc - m);
            s += w;
        }
        const float4* vp = (const float4*)&vs[j][0];
        float4 b0 = vp[0], b1 = vp[1], b2 = vp[2], b3 = vp[3];
        acc[0]  += w*b0.x; acc[1]  += w*b0.y; acc[2]  += w*b0.z; acc[3]  += w*b0.w;
        acc[4]  += w*b1.x; acc[5]  += w*b1.y; acc[6]  += w*b1.z; acc[7]  += w*b1.w;
        acc[8]  += w*b2.x; acc[9]  += w*b2.y; acc[10] += w*b2.z; acc[11] += w*b2.w;
        acc[12] += w*b3.x; acc[13] += w*b3.y; acc[14] += w*b3.z; acc[15] += w*b3.w;
    }
    if (!myv) {
        for (int j = 0; j < L; j++) {
            bool inv_key = SPATIAL ? (!vm[j]) : (j >= len);
            if (!inv_key) continue;
            s += 1.f;
            const float4* vp = (const float4*)&vs[j][0];
            float4 b0 = vp[0], b1 = vp[1], b2 = vp[2], b3 = vp[3];
            acc[0]  += b0.x; acc[1]  += b0.y; acc[2]  += b0.z; acc[3]  += b0.w;
            acc[4]  += b1.x; acc[5]  += b1.y; acc[6]  += b1.z; acc[7]  += b1.w;
            acc[8]  += b2.x; acc[9]  += b2.y; acc[10] += b2.z; acc[11] += b2.w;
            acc[12] += b3.x; acc[13] += b3.y; acc[14] += b3.z; acc[15] += b3.w;
        }
    }
    float inv = 1.f / s;
    __syncthreads();
    #pragma unroll
    for (int dd = 0; dd < DH_; dd++) qs[i][dd] = acc[dd] * inv;
    __syncthreads();
    #pragma unroll
    for (int x = 0; x < 4; x++) {
        int idx = x * L + i;
        int j = idx >> 2, q = (idx & 3) * 4;
        *(float4*)(O + (rowbase + j) * H_ + coff + q) = *(const float4*)&qs[j][q];
    }
}

__global__ __launch_bounds__(T_) void attn_t0_kernel(
    const float* __restrict__ Qs, const float* __restrict__ Km,
    const float* __restrict__ Vm, float* __restrict__ O,
    const int* __restrict__ lengths, int ldkv)
{
    const int head = blockIdx.x, n = blockIdx.y, j = threadIdx.x;
    __shared__ float sw[T_];
    const int len = lengths[n], coff = head * DH_;
    const float* qp = Qs + (size_t)n * H_ + coff;
    const float* kp = Km + ((size_t)n * T_ + j) * ldkv + coff;
    float d = 0.f;
    #pragma unroll
    for (int dd = 0; dd < DH_; dd++) d += qp[dd] * kp[dd];
    float sc = (j < len) ? d * SCALE_ : -1e9f;
    sw[j] = sc;
    __syncthreads();
    float m = -1e30f;
    #pragma unroll 8
    for (int jj = 0; jj < T_; jj++) m = fmaxf(m, sw[jj]);
    float w = __expf(sc - m);
    __syncthreads();
    sw[j] = w;
    __syncthreads();
    if (j < DH_) {
        float s = 0.f, acc = 0.f;
        for (int jj = 0; jj < T_; jj++) {
            float wj = sw[jj];
            s += wj;
            acc += wj * Vm[((size_t)n * T_ + jj) * ldkv + coff + j];
        }
        O[(size_t)n * H_ + coff + j] = acc / s;
    }
}

__global__ void gather_t0_kernel(const float* __restrict__ X, float* __restrict__ Xg)
{
    int idx = blockIdx.x * blockDim.x + threadIdx.x;
    if (idx >= MS_ * H_) return;
    Xg[idx] = X[((size_t)(idx / H_) * T_) * H_ + (idx % H_)];
}
__global__ void final_kernel(const float* __restrict__ Xs, float* __restrict__ out)
{
    int idx = blockIdx.x * blockDim.x + threadIdx.x;
    if (idx >= B_ * T_ * H_) return;
    int h = idx % H_, t = (idx / H_) % T_, b = idx / (T_ * H_);
    out[idx] = Xs[((size_t)b * S_ + t) * H_ + h];
}

// ---------------- host ----------------
#define PGRID_ 152
#define ATTN_SMEM (3 * 64 * ROWF * 16)
static void tcP(const float* A, float* C, const float* bias, const float* res,
                const float* lns, const float* lnb, const float* pos, const int* len,
                int ntiles, int mode, int tileB, int padA, int ldC, int n0)
{
    tc_pgemm<<<PGRID_, 512, PT_SMEM + 1024>>>(A, C, bias, res, lns, lnb, pos, len,
                                              ntiles, mode, tileB, padA, ldC, n0);
}
static void tcG(const float* A, float* C, const float* b0, const float* b1p,
                const float* b2p, const float* res, const float* lns, const float* lnb,
                int M, int KC, int NT, int mode, int tile0)
{
    dim3 g(M / 128, NT);
    tc_gemm<<<g, 512, SG_SMEM + 1024>>>(A, C, b0, b1p, b2p, res, lns, lnb,
                                        KC, NT, mode, tile0);
}

extern "C" void kernel_launch(void* const* d_in, const int* in_sizes, int n_in,
                              void* d_out, int out_size)
{
    const float* poly = (const float*)d_in[0];
    const int*   len  = (const int*)  d_in[1];
    const float* pw   = (const float*)d_in[2];
    const float* pb   = (const float*)d_in[3];
    const float* pls  = (const float*)d_in[4];
    const float* plb  = (const float*)d_in[5];
    const float* pos  = (const float*)d_in[6];
    const float* Wq   = (const float*)d_in[7];
    const float* bq   = (const float*)d_in[8];
    const float* Wk   = (const float*)d_in[9];
    const float* bk   = (const float*)d_in[10];
    const float* Wv   = (const float*)d_in[11];
    const float* bv   = (const float*)d_in[12];
    const float* Wo   = (const float*)d_in[13];
    const float* bo   = (const float*)d_in[14];
    const float* l1s  = (const float*)d_in[15];
    const float* l1b  = (const float*)d_in[16];
    const float* W1   = (const float*)d_in[17];
    const float* b1   = (const float*)d_in[18];
    const float* W2   = (const float*)d_in[19];
    const float* b2   = (const float*)d_in[20];
    const float* l2s  = (const float*)d_in[21];
    const float* l2b  = (const float*)d_in[22];
    float* out = (float*)d_out;

    cudaFuncSetAttribute(tc_gemm, cudaFuncAttributeMaxDynamicSharedMemorySize, SG_SMEM + 1024);
    cudaFuncSetAttribute(tc_pgemm, cudaFuncAttributeMaxDynamicSharedMemorySize, PT_SMEM + 1024);
    cudaFuncSetAttribute(tc_pgemm2, cudaFuncAttributeMaxDynamicSharedMemorySize, P2_SMEM + 1024);
    cudaFuncSetAttribute(tc_pffn, cudaFuncAttributeMaxDynamicSharedMemorySize, PF_SMEM + 1024);
    cudaFuncSetAttribute(attn_seq_kernel, cudaFuncAttributeMaxDynamicSharedMemorySize, ATTN_SMEM);

    float *x, *tmp, *q, *hb, *xs, *qs, *qkv, *ts;
    cudaGetSymbolAddress((void**)&x, g_x);   cudaGetSymbolAddress((void**)&tmp, g_tmp);
    cudaGetSymbolAddress((void**)&q, g_q);   cudaGetSymbolAddress((void**)&hb, g_h);
    cudaGetSymbolAddress((void**)&xs, g_xs); cudaGetSymbolAddress((void**)&qs, g_qs);
    cudaGetSymbolAddress((void**)&qkv, g_qkv);
    cudaGetSymbolAddress((void**)&ts, g_ts);

    const int NTIL0 = M0_ / 128;  // 1024
    const int NTILS = MS_ / 128;  // 16

    PrepArgs pa{pw, Wq, Wk, Wv, Wo, W1, W2};
    prep_kernel<<<NTILES_, 256>>>(pa);

    // embed: proj (pad fused) + LN + relu + pos
    tcP(poly, x, pb, nullptr, pls, plb, pos, len, NTIL0, 3, 0, 1, 128, 0);

    // block 0 (temporal, full); tiles 1..8
    tcP(x, q, bq, nullptr, nullptr, nullptr, nullptr, nullptr, NTIL0, 0, 1, 0, 128, 0);
    tc_pgemm2<<<PGRID_, 512, P2_SMEM + 1024>>>(x, hb, bk, bv, NTIL0, 0, 2);
    attn_seq_kernel<<<B_ * S_, 512, ATTN_SMEM>>>(q, hb, hb + 128, tmp, len, 256);
    tcP(tmp, x, bo, x, l1s, l1b, nullptr, nullptr, NTIL0, 2, 4, 0, 128, 0);
    tc_pffn<<<PGRID_, 512, PF_SMEM + 1024>>>(x, NTIL0, 5, 7, b1, b2, l2s, l2b);

    // block 1 (temporal; K/V full, rest t=0 only); tiles 9..16
    {
        tc_pgemm2<<<PGRID_, 512, P2_SMEM + 1024>>>(x, hb, bk + H_, bv + H_, NTIL0, 0, 10);
        gather_t0_kernel<<<(MS_ * H_ + 255) / 256, 256>>>(x, xs);
        tcG(xs, qs, bq + H_, nullptr, nullptr, nullptr, nullptr, nullptr, MS_, 1, 1, 0, 9);
        attn_t0_kernel<<<dim3(NH_, MS_), T_>>>(qs, hb, hb + 128, ts, len, 256);
        tcG(ts, xs, bo + H_, nullptr, nullptr, xs, l1s + H_, l1b + H_, MS_, 1, 1, 2, 12);
        tc_pffn<<<NTILS, 512, PF_SMEM + 1024>>>(xs, NTILS, 13, 15, b1 + FF_, b2 + H_, l2s + H_, l2b + H_);
    }

    // blocks 2,3 (spatial compact)
    for (int i = 2; i < 4; i++) {
        const int t0 = 1 + i * 8;
        tcG(xs, qkv, bq + i * H_, bk + i * H_, bv + i * H_, nullptr, nullptr, nullptr,
            MS_, 1, 3, 0, t0);
        attn_kernel<S_, true><<<dim3(NH_, B_), S_>>>(qkv, qkv + 128, qkv + 256, ts, len, 384);
        tcG(ts, xs, bo + i * H_, nullptr, nullptr, xs, l1s + i * H_, l1b + i * H_, MS_, 1, 1, 2, t0 + 3);
        tc_pffn<<<NTILS, 512, PF_SMEM + 1024>>>(xs, NTILS, t0 + 4, t0 + 6,
                                                b1 + i * FF_, b2 + i * H_, l2s + i * H_, l2b + i * H_);
    }

    final_kernel<<<(B_ * T_ * H_ + 255) / 256, 256>>>(xs, out);
    (void)in_sizes; (void)n_in; (void)out_size;
}